// round 13
// baseline (speedup 1.0000x reference)
#include <cuda_runtime.h>
#include <cuda_fp16.h>
#include <math.h>
#include <stdint.h>

// Problem dims (fixed)
#define BB   2
#define TT   2048
#define CC   1024
#define EE   1024
#define HH   16
#define HS   64
#define FF   4096
#define MM   (BB*TT)   // 4096 rows
#define QKV  (3*EE)    // 3072

// ======================= scratch (static device globals) ===================
__device__ float g_tmp [MM*CC];
__device__ float g_out1[MM*CC];
__device__ float g_out2[MM*CC];
__device__ float g_bqkv[QKV];

__device__ __half g_x16 [MM*CC];
__device__ __half g_qkv [MM*QKV];
__device__ __half g_a16 [MM*EE];
__device__ __half g_o116[MM*CC];
__device__ __half g_f16 [MM*FF];
__device__ __half g_o216[MM*CC];
// transposed weights: [N, K] fp16
__device__ __half g_wqkv[QKV*CC];
__device__ __half g_wo  [CC*EE];
__device__ __half g_w1  [FF*CC];
__device__ __half g_w2  [CC*FF];
__device__ __half g_wc  [CC*CC];

// ======================= small PTX helpers =================================
__device__ __forceinline__ uint32_t smem_u32(const void* p) {
    uint32_t a;
    asm("{ .reg .u64 t; cvta.to.shared.u64 t, %1; cvt.u32.u64 %0, t; }"
        : "=r"(a) : "l"(p));
    return a;
}
__device__ __forceinline__ void cp16(uint32_t saddr, const void* gaddr) {
    asm volatile("cp.async.cg.shared.global [%0], [%1], 16;"
                 :: "r"(saddr), "l"(gaddr) : "memory");
}
#define CP_COMMIT() asm volatile("cp.async.commit_group;" ::: "memory")
#define CP_WAIT(n)  asm volatile("cp.async.wait_group %0;" :: "n"(n) : "memory")

__device__ __forceinline__ void ldsm_x4(uint32_t r[4], uint32_t addr) {
    asm volatile("ldmatrix.sync.aligned.m8n8.x4.shared.b16 {%0,%1,%2,%3}, [%4];"
                 : "=r"(r[0]), "=r"(r[1]), "=r"(r[2]), "=r"(r[3]) : "r"(addr));
}
__device__ __forceinline__ void ldsm_x4_t(uint32_t r[4], uint32_t addr) {
    asm volatile("ldmatrix.sync.aligned.m8n8.x4.trans.shared.b16 {%0,%1,%2,%3}, [%4];"
                 : "=r"(r[0]), "=r"(r[1]), "=r"(r[2]), "=r"(r[3]) : "r"(addr));
}
// fp32-accum MMA (attention)
__device__ __forceinline__ void mma16816(float c[4],
    uint32_t a0, uint32_t a1, uint32_t a2, uint32_t a3, uint32_t b0, uint32_t b1)
{
    asm volatile(
        "mma.sync.aligned.m16n8k16.row.col.f32.f16.f16.f32 "
        "{%0,%1,%2,%3}, {%4,%5,%6,%7}, {%8,%9}, {%0,%1,%2,%3};"
        : "+f"(c[0]), "+f"(c[1]), "+f"(c[2]), "+f"(c[3])
        : "r"(a0), "r"(a1), "r"(a2), "r"(a3), "r"(b0), "r"(b1));
}
// fp16-accum MMA (GEMM inner chunks, 2x rate hypothesis)
__device__ __forceinline__ void mma16816_h(uint32_t c[2],
    uint32_t a0, uint32_t a1, uint32_t a2, uint32_t a3, uint32_t b0, uint32_t b1)
{
    asm volatile(
        "mma.sync.aligned.m16n8k16.row.col.f16.f16.f16.f16 "
        "{%0,%1}, {%2,%3,%4,%5}, {%6,%7}, {%0,%1};"
        : "+r"(c[0]), "+r"(c[1])
        : "r"(a0), "r"(a1), "r"(a2), "r"(a3), "r"(b0), "r"(b1));
}
__device__ __forceinline__ uint32_t packh(__half a, __half b) {
    __half2 t = __halves2half2(a, b);
    return *(uint32_t*)&t;
}
__device__ __forceinline__ float ex2(float x) {
    float y;
    asm("ex2.approx.f32 %0, %1;" : "=f"(y) : "f"(x));
    return y;
}

// ======================= fused prep kernel =================================
__device__ __forceinline__ void transpose_block(
    const float* __restrict__ W, __half* __restrict__ T,
    int K, int N, int bb, float (*t)[33])
{
    const int nb = N >> 5;
    const int bx = bb % nb, by = bb / nb;
    const int n0 = bx * 32, k0 = by * 32;
    const int tx = threadIdx.x & 31, ty = threadIdx.x >> 5;
    #pragma unroll
    for (int s = 0; s < 32; s += 8)
        t[ty + s][tx] = W[(size_t)(k0 + ty + s) * N + n0 + tx];
    __syncthreads();
    #pragma unroll
    for (int s = 0; s < 32; s += 8)
        T[(size_t)(n0 + ty + s) * K + k0 + tx] = __float2half_rn(t[tx][ty + s]);
}
__device__ __forceinline__ void convert_block(
    const float* __restrict__ in, __half* __restrict__ o, int bb)
{
    const int idx = bb * 1024 + threadIdx.x * 4;
    float4 v = *(const float4*)(in + idx);
    *(__half2*)(o + idx)     = __halves2half2(__float2half_rn(v.x), __float2half_rn(v.y));
    *(__half2*)(o + idx + 2) = __halves2half2(__float2half_rn(v.z), __float2half_rn(v.w));
}

#define PREP_GRID 17411

__global__ __launch_bounds__(256) void prep_all(
    const float* __restrict__ Wq, const float* __restrict__ Wk,
    const float* __restrict__ Wv, const float* __restrict__ Wo,
    const float* __restrict__ W1, const float* __restrict__ W2,
    const float* __restrict__ Wc, const float* __restrict__ x,
    const float* __restrict__ bq, const float* __restrict__ bk,
    const float* __restrict__ bv,
    __half* __restrict__ wqkv, __half* __restrict__ wo,
    __half* __restrict__ w1,   __half* __restrict__ w2,
    __half* __restrict__ wc,   __half* __restrict__ x16,
    float* __restrict__ bqkv)
{
    __shared__ float t[32][33];
    const int b = blockIdx.x;
    if (b < 3072) {
        const int seg = b >> 10, bb = b & 1023;
        const float* W = (seg == 0) ? Wq : (seg == 1) ? Wk : Wv;
        transpose_block(W, wqkv + (size_t)seg * EE * CC, CC, EE, bb, t);
    } else if (b < 4096) {
        transpose_block(Wo, wo, EE, CC, b - 3072, t);
    } else if (b < 8192) {
        transpose_block(W1, w1, CC, FF, b - 4096, t);
    } else if (b < 12288) {
        transpose_block(W2, w2, FF, CC, b - 8192, t);
    } else if (b < 13312) {
        convert_block(Wc, wc, b - 12288);
    } else if (b < 17408) {
        convert_block(x, x16, b - 13312);
    } else {
        const int bb = b - 17408;
        const float* src = (bb == 0) ? bq : (bb == 1) ? bk : bv;
        ((float4*)(bqkv + bb * EE))[threadIdx.x] = ((const float4*)src)[threadIdx.x];
    }
}

// ======================= swizzle (128B rows, 8 x 16B chunks) ===============
__device__ __forceinline__ uint32_t sw8(int row, int ch) {
    return (uint32_t)(row * 128 + ((ch ^ (row & 7)) << 4));
}

// ======================= HMMA GEMM: fp16-accum chunks + fp32 promote =======
// C[M,N] = A[M,K] @ B[N,K]^T + bias.
// CTA tile 128x128, BK=64, 256 threads (8 warps, warp tile 64x32).
// Each 64-wide chunk accumulates in fp16 (4 chained fp16-accum MMAs, 2x rate),
// then promotes into fp32 master registers once per chunk.
// 2-stage cp.async double buffer, ONE __syncthreads per chunk.
#define STAGE_BYTES 32768
#define ARR_A 0
#define ARR_B 16384
#define GEMM_SMEM (2*STAGE_BYTES)

template<int GELU, int WF32, int WH>
__global__ __launch_bounds__(256, 2) void gemm_mma(
    const __half* __restrict__ A, const __half* __restrict__ Bw,
    const float* __restrict__ bias,
    float* __restrict__ Cf, __half* __restrict__ Ch,
    int M, int N, int K)
{
    extern __shared__ char sm[];
    const uint32_t su = smem_u32(sm);

    const int tid  = threadIdx.x;
    const int wid  = tid >> 5;
    const int lane = tid & 31;
    const int m0 = blockIdx.y * 128;
    const int n0 = blockIdx.x * 128;
    const int wm0 = (wid & 1) * 64;
    const int wn0 = (wid >> 1) * 32;

    float acc[4][4][4];   // fp32 master
    #pragma unroll
    for (int mt = 0; mt < 4; mt++)
        #pragma unroll
        for (int nt = 0; nt < 4; nt++)
            #pragma unroll
            for (int i = 0; i < 4; i++) acc[mt][nt][i] = 0.f;

    const int nCh = K >> 6;   // 64-wide chunks

    auto issue = [&](int c, int stg) {
        const uint32_t sbase = su + stg * STAGE_BYTES;
        #pragma unroll
        for (int i = 0; i < 4; i++) {
            const int vec = tid + i * 256;       // 0..1023
            const int row = vec >> 3;            // 0..127
            const int ch  = vec & 7;             // 16B chunk in 128B row
            const uint32_t so = sw8(row, ch);
            const size_t gA = ((size_t)(m0 + row) * K + c * 64 + ch * 8) * 2;
            const size_t gB = ((size_t)(n0 + row) * K + c * 64 + ch * 8) * 2;
            cp16(sbase + ARR_A + so, (const char*)A  + gA);
            cp16(sbase + ARR_B + so, (const char*)Bw + gB);
        }
    };

    issue(0, 0);
    CP_COMMIT();

    const int grp = lane >> 3, wi = lane & 7;

    for (int c = 0; c < nCh; c++) {
        const int stg = c & 1;
        CP_WAIT(0);
        __syncthreads();
        if (c + 1 < nCh) {
            issue(c + 1, stg ^ 1);
            CP_COMMIT();
        }

        const uint32_t sbase = su + stg * STAGE_BYTES;

        // fp16 chunk accumulators (zeroed per chunk)
        uint32_t hacc[4][4][2];
        #pragma unroll
        for (int mt = 0; mt < 4; mt++)
            #pragma unroll
            for (int nt = 0; nt < 4; nt++) {
                hacc[mt][nt][0] = 0u;
                hacc[mt][nt][1] = 0u;
            }

        #pragma unroll
        for (int ks = 0; ks < 4; ks++) {
            uint32_t bfr[4][2];
            const int brow_base = wn0 + wi + ((grp >> 1) << 3);
            const int bchunk = ks * 2 + (grp & 1);
            #pragma unroll
            for (int bt = 0; bt < 2; bt++) {
                uint32_t r4[4];
                const int br = brow_base + bt * 16;
                ldsm_x4(r4, sbase + ARR_B + sw8(br, bchunk));
                bfr[bt*2][0]   = r4[0]; bfr[bt*2][1]   = r4[1];
                bfr[bt*2+1][0] = r4[2]; bfr[bt*2+1][1] = r4[3];
            }

            const int arow = wm0 + (lane & 15);
            const int achunk = ks * 2 + (lane >> 4);
            uint32_t a[4][4];
            #pragma unroll
            for (int mt = 0; mt < 4; mt++)
                ldsm_x4(a[mt], sbase + ARR_A + sw8(arow + mt * 16, achunk));
            #pragma unroll
            for (int mt = 0; mt < 4; mt++)
                #pragma unroll
                for (int nt = 0; nt < 4; nt++)
                    mma16816_h(hacc[mt][nt], a[mt][0], a[mt][1], a[mt][2], a[mt][3],
                               bfr[nt][0], bfr[nt][1]);
        }

        // promote chunk partial into fp32 master (overlaps next chunk's loads)
        #pragma unroll
        for (int mt = 0; mt < 4; mt++)
            #pragma unroll
            for (int nt = 0; nt < 4; nt++) {
                float2 lo = __half22float2(*(__half2*)&hacc[mt][nt][0]);
                float2 hi = __half22float2(*(__half2*)&hacc[mt][nt][1]);
                acc[mt][nt][0] += lo.x;
                acc[mt][nt][1] += lo.y;
                acc[mt][nt][2] += hi.x;
                acc[mt][nt][3] += hi.y;
            }
    }

    const int er = lane >> 2;
    const int ec = (lane & 3) * 2;
    #pragma unroll
    for (int mt = 0; mt < 4; mt++) {
        #pragma unroll
        for (int nt = 0; nt < 4; nt++) {
            const int col = n0 + wn0 + nt * 8 + ec;
            const float b0 = bias[col], b1 = bias[col + 1];
            const int rA = m0 + wm0 + mt * 16 + er;
            const int rB = rA + 8;
            float v00 = acc[mt][nt][0] + b0;
            float v01 = acc[mt][nt][1] + b1;
            float v10 = acc[mt][nt][2] + b0;
            float v11 = acc[mt][nt][3] + b1;
            if (GELU) {
                v00 = 0.5f * v00 * (1.0f + erff(v00 * 0.70710678118654752f));
                v01 = 0.5f * v01 * (1.0f + erff(v01 * 0.70710678118654752f));
                v10 = 0.5f * v10 * (1.0f + erff(v10 * 0.70710678118654752f));
                v11 = 0.5f * v11 * (1.0f + erff(v11 * 0.70710678118654752f));
            }
            if (WF32) {
                *(float2*)(Cf + (size_t)rA * N + col) = make_float2(v00, v01);
                *(float2*)(Cf + (size_t)rB * N + col) = make_float2(v10, v11);
            }
            if (WH) {
                *(__half2*)(Ch + (size_t)rA * N + col) =
                    __halves2half2(__float2half_rn(v00), __float2half_rn(v01));
                *(__half2*)(Ch + (size_t)rB * N + col) =
                    __halves2half2(__float2half_rn(v10), __float2half_rn(v11));
            }
        }
    }
}

// ======================= tensor-core flash attention (R11) =================
#define ASM_Q   0
#define KBUF(b) (16384 + (b) * 16384)
#define VBUF(b) (16384 + (b) * 16384 + 8192)
#define ATTN_SMEM 49152
#define NSCH (TT/64)   // 32
#define SCALE2 0.18033688011112042f   // 0.125 * log2(e)

__global__ void __launch_bounds__(256, 2) attn_mma(
    const __half* __restrict__ QKVp, __half* __restrict__ O)
{
    extern __shared__ char sm[];
    const uint32_t su = smem_u32(sm);

    const int tid  = threadIdx.x;
    const int wid  = tid >> 5;
    const int lane = tid & 31;
    const int q0 = blockIdx.x * 128;
    const int bh = blockIdx.y;
    const int b  = bh >> 4;
    const int h  = bh & 15;
    const size_t mrow0 = (size_t)b * TT;
    const size_t qbase = (mrow0 + q0) * QKV + h * HS;

    const int wm  = wid * 16;
    const int grp = lane >> 3, wi = lane & 7;

    #pragma unroll
    for (int i = 0; i < 4; i++) {
        int vec = tid + i * 256;
        int row = vec >> 3, ch = vec & 7;
        const size_t g = (qbase + (size_t)row * QKV + ch * 8) * 2;
        cp16(su + ASM_Q + sw8(row, ch), (const char*)QKVp + g);
    }
    CP_COMMIT();

    auto issueKV = [&](int s, int stg) {
        const size_t kb = ((mrow0 + (size_t)s * 64) * QKV + EE + h * HS) * 2;
        #pragma unroll
        for (int i = 0; i < 2; i++) {
            int vec = tid + i * 256;
            int row = vec >> 3, ch = vec & 7;
            const size_t off = ((size_t)row * QKV + ch * 8) * 2;
            cp16(su + KBUF(stg) + sw8(row, ch), (const char*)QKVp + kb + off);
            cp16(su + VBUF(stg) + sw8(row, ch), (const char*)QKVp + kb + EE*2 + off);
        }
    };
    issueKV(0, 0);
    CP_COMMIT();

    float m0 = -1e30f, m1 = -1e30f, l0 = 0.f, l1 = 0.f;
    float oacc[8][4];
    #pragma unroll
    for (int nt = 0; nt < 8; nt++)
        #pragma unroll
        for (int i = 0; i < 4; i++) oacc[nt][i] = 0.f;

    for (int s = 0; s < NSCH; s++) {
        const int stg = s & 1;
        CP_WAIT(0);
        __syncthreads();
        if (s + 1 < NSCH) {
            issueKV(s + 1, stg ^ 1);
            CP_COMMIT();
        }

        const uint32_t kbase = su + KBUF(stg);
        const uint32_t vbase = su + VBUF(stg);

        float sacc[8][4];
        #pragma unroll
        for (int nt = 0; nt < 8; nt++)
            #pragma unroll
            for (int i = 0; i < 4; i++) sacc[nt][i] = 0.f;

        #pragma unroll
        for (int ks = 0; ks < 4; ks++) {
            const int arow = wm + (lane & 15);
            const int achunk = ks * 2 + (lane >> 4);
            uint32_t qa[4];
            ldsm_x4(qa, su + ASM_Q + sw8(arow, achunk));

            uint32_t kf[8][2];
            #pragma unroll
            for (int bt = 0; bt < 4; bt++) {
                const int br = wi + ((grp >> 1) << 3) + bt * 16;
                const int bch = ks * 2 + (grp & 1);
                uint32_t r4[4];
                ldsm_x4(r4, kbase + sw8(br, bch));
                kf[bt*2][0] = r4[0]; kf[bt*2][1] = r4[1];
                kf[bt*2+1][0] = r4[2]; kf[bt*2+1][1] = r4[3];
            }
            #pragma unroll
            for (int nt = 0; nt < 8; nt++)
                mma16816(sacc[nt], qa[0], qa[1], qa[2], qa[3], kf[nt][0], kf[nt][1]);
        }

        float rmax0 = -1e30f, rmax1 = -1e30f;
        #pragma unroll
        for (int nt = 0; nt < 8; nt++) {
            #pragma unroll
            for (int i = 0; i < 4; i++) sacc[nt][i] *= SCALE2;
            rmax0 = fmaxf(rmax0, fmaxf(sacc[nt][0], sacc[nt][1]));
            rmax1 = fmaxf(rmax1, fmaxf(sacc[nt][2], sacc[nt][3]));
        }
        #pragma unroll
        for (int msk = 1; msk < 4; msk <<= 1) {
            rmax0 = fmaxf(rmax0, __shfl_xor_sync(0xffffffffu, rmax0, msk));
            rmax1 = fmaxf(rmax1, __shfl_xor_sync(0xffffffffu, rmax1, msk));
        }
        const float nm0 = fmaxf(m0, rmax0);
        const float nm1 = fmaxf(m1, rmax1);
        const float corr0 = ex2(m0 - nm0);
        const float corr1 = ex2(m1 - nm1);

        uint32_t pa[4][4];
        float sum0 = 0.f, sum1 = 0.f;
        #pragma unroll
        for (int nt = 0; nt < 8; nt++) {
            float p0 = ex2(sacc[nt][0] - nm0);
            float p1 = ex2(sacc[nt][1] - nm0);
            float p2 = ex2(sacc[nt][2] - nm1);
            float p3 = ex2(sacc[nt][3] - nm1);
            sum0 += p0 + p1;
            sum1 += p2 + p3;
            const int kt = nt >> 1, hf = nt & 1;
            pa[kt][hf*2]   = packh(__float2half_rn(p0), __float2half_rn(p1));
            pa[kt][hf*2+1] = packh(__float2half_rn(p2), __float2half_rn(p3));
        }
        #pragma unroll
        for (int msk = 1; msk < 4; msk <<= 1) {
            sum0 += __shfl_xor_sync(0xffffffffu, sum0, msk);
            sum1 += __shfl_xor_sync(0xffffffffu, sum1, msk);
        }
        l0 = l0 * corr0 + sum0;
        l1 = l1 * corr1 + sum1;
        m0 = nm0; m1 = nm1;
        #pragma unroll
        for (int nt = 0; nt < 8; nt++) {
            oacc[nt][0] *= corr0; oacc[nt][1] *= corr0;
            oacc[nt][2] *= corr1; oacc[nt][3] *= corr1;
        }

        #pragma unroll
        for (int ks = 0; ks < 4; ks++) {
            uint32_t vf[8][2];
            #pragma unroll
            for (int bt = 0; bt < 4; bt++) {
                const int key_row = ks * 16 + (grp & 1) * 8 + wi;
                const int dim_ch  = bt * 2 + (grp >> 1);
                uint32_t r4[4];
                ldsm_x4_t(r4, vbase + sw8(key_row, dim_ch));
                vf[bt*2][0] = r4[0]; vf[bt*2][1] = r4[1];
                vf[bt*2+1][0] = r4[2]; vf[bt*2+1][1] = r4[3];
            }
            #pragma unroll
            for (int nt = 0; nt < 8; nt++)
                mma16816(oacc[nt], pa[ks][0], pa[ks][1], pa[ks][2], pa[ks][3],
                         vf[nt][0], vf[nt][1]);
        }
    }

    const float inv0 = 1.0f / l0;
    const float inv1 = 1.0f / l1;
    const int r = lane >> 2;
    const int qcol = 2 * (lane & 3);
    const size_t row0 = (mrow0 + q0 + wm + r) * EE + h * HS;
    const size_t row1 = row0 + (size_t)8 * EE;
    #pragma unroll
    for (int nt = 0; nt < 8; nt++) {
        const int col = nt * 8 + qcol;
        *(__half2*)(O + row0 + col) = __halves2half2(
            __float2half_rn(oacc[nt][0] * inv0), __float2half_rn(oacc[nt][1] * inv0));
        *(__half2*)(O + row1 + col) = __halves2half2(
            __float2half_rn(oacc[nt][2] * inv1), __float2half_rn(oacc[nt][3] * inv1));
    }
}

// ======================= residual add + LayerNorm ==========================
__global__ __launch_bounds__(256) void add_ln(
    const float* __restrict__ a, const float* __restrict__ bsrc,
    const float* __restrict__ g, const float* __restrict__ beta,
    float* __restrict__ out, __half* __restrict__ oh)
{
    const int row = blockIdx.x;
    const int tid = threadIdx.x;
    const float4 av = ((const float4*)(a    + (size_t)row * CC))[tid];
    const float4 bv = ((const float4*)(bsrc + (size_t)row * CC))[tid];
    float4 v = make_float4(av.x + bv.x, av.y + bv.y, av.z + bv.z, av.w + bv.w);

    float s  = v.x + v.y + v.z + v.w;
    float ss = v.x*v.x + v.y*v.y + v.z*v.z + v.w*v.w;
    #pragma unroll
    for (int msk = 16; msk; msk >>= 1) {
        s  += __shfl_xor_sync(0xffffffffu, s,  msk);
        ss += __shfl_xor_sync(0xffffffffu, ss, msk);
    }
    __shared__ float ws[8], wss[8];
    __shared__ float mu_s, rstd_s;
    const int w = tid >> 5, lane = tid & 31;
    if (lane == 0) { ws[w] = s; wss[w] = ss; }
    __syncthreads();
    if (tid == 0) {
        float S = 0.f, SS = 0.f;
        #pragma unroll
        for (int i = 0; i < 8; i++) { S += ws[i]; SS += wss[i]; }
        float mu  = S * (1.0f / CC);
        float var = SS * (1.0f / CC) - mu * mu;
        mu_s   = mu;
        rstd_s = rsqrtf(var + 1e-5f);
    }
    __syncthreads();
    const float mu = mu_s, rstd = rstd_s;
    const float4 gv = ((const float4*)g)[tid];
    const float4 bv2 = ((const float4*)beta)[tid];
    float4 ov;
    ov.x = (v.x - mu) * rstd * gv.x + bv2.x;
    ov.y = (v.y - mu) * rstd * gv.y + bv2.y;
    ov.z = (v.z - mu) * rstd * gv.z + bv2.z;
    ov.w = (v.w - mu) * rstd * gv.w + bv2.w;
    ((float4*)(out + (size_t)row * CC))[tid] = ov;

    if (oh) {
        size_t o = (size_t)row * CC + tid * 4;
        *(__half2*)(oh + o)     = __halves2half2(__float2half_rn(ov.x), __float2half_rn(ov.y));
        *(__half2*)(oh + o + 2) = __halves2half2(__float2half_rn(ov.z), __float2half_rn(ov.w));
    }
}

// ======================= launch ============================================
extern "C" void kernel_launch(void* const* d_in, const int* in_sizes, int n_in,
                              void* d_out, int out_size)
{
    const float* x     = (const float*)d_in[0];
    const float* Wq    = (const float*)d_in[1];
    const float* bq    = (const float*)d_in[2];
    const float* Wk    = (const float*)d_in[3];
    const float* bk    = (const float*)d_in[4];
    const float* Wv    = (const float*)d_in[5];
    const float* bv    = (const float*)d_in[6];
    const float* Wo    = (const float*)d_in[7];
    const float* bo    = (const float*)d_in[8];
    const float* ln1_g = (const float*)d_in[9];
    const float* ln1_b = (const float*)d_in[10];
    const float* W1    = (const float*)d_in[11];
    const float* b1    = (const float*)d_in[12];
    const float* W2    = (const float*)d_in[13];
    const float* b2    = (const float*)d_in[14];
    const float* ln2_g = (const float*)d_in[15];
    const float* ln2_b = (const float*)d_in[16];
    const float* Wc    = (const float*)d_in[17];
    const float* bc    = (const float*)d_in[18];
    float* out = (float*)d_out;

    float *tmp, *out1, *out2, *bqkv;
    cudaGetSymbolAddress((void**)&tmp,  g_tmp);
    cudaGetSymbolAddress((void**)&out1, g_out1);
    cudaGetSymbolAddress((void**)&out2, g_out2);
    cudaGetSymbolAddress((void**)&bqkv, g_bqkv);

    __half *x16,*qkv,*a16,*o116,*f16,*o216,*wqkv,*wo,*w1,*w2,*wc;
    cudaGetSymbolAddress((void**)&x16,  g_x16);
    cudaGetSymbolAddress((void**)&qkv,  g_qkv);
    cudaGetSymbolAddress((void**)&a16,  g_a16);
    cudaGetSymbolAddress((void**)&o116, g_o116);
    cudaGetSymbolAddress((void**)&f16,  g_f16);
    cudaGetSymbolAddress((void**)&o216, g_o216);
    cudaGetSymbolAddress((void**)&wqkv, g_wqkv);
    cudaGetSymbolAddress((void**)&wo,   g_wo);
    cudaGetSymbolAddress((void**)&w1,   g_w1);
    cudaGetSymbolAddress((void**)&w2,   g_w2);
    cudaGetSymbolAddress((void**)&wc,   g_wc);

    cudaFuncSetAttribute(gemm_mma<0,1,0>,
                         cudaFuncAttributeMaxDynamicSharedMemorySize, GEMM_SMEM);
    cudaFuncSetAttribute(gemm_mma<0,0,1>,
                         cudaFuncAttributeMaxDynamicSharedMemorySize, GEMM_SMEM);
    cudaFuncSetAttribute(gemm_mma<1,0,1>,
                         cudaFuncAttributeMaxDynamicSharedMemorySize, GEMM_SMEM);
    cudaFuncSetAttribute(attn_mma,
                         cudaFuncAttributeMaxDynamicSharedMemorySize, ATTN_SMEM);

    // --- all prep in ONE launch ---
    prep_all<<<PREP_GRID, 256>>>(Wq, Wk, Wv, Wo, W1, W2, Wc, x, bq, bk, bv,
                                 wqkv, wo, w1, w2, wc, x16, bqkv);

    // --- fused QKV projection (N = 3072) ---
    const dim3 gQKV(QKV/128, MM/128);
    const dim3 gC(CC/128, MM/128);
    const dim3 gF(FF/128, MM/128);
    gemm_mma<0,0,1><<<gQKV, 256, GEMM_SMEM>>>(x16, wqkv, bqkv, nullptr, qkv, MM, QKV, CC);

    // --- attention ---
    attn_mma<<<dim3(TT/128, BB*HH), 256, ATTN_SMEM>>>(qkv, a16);

    // --- output projection + residual + LN1 ---
    gemm_mma<0,1,0><<<gC, 256, GEMM_SMEM>>>(a16, wo, bo, tmp, nullptr, MM, CC, EE);
    add_ln<<<MM, 256>>>(x, tmp, ln1_g, ln1_b, out1, o116);

    // --- FFN ---
    gemm_mma<1,0,1><<<gF, 256, GEMM_SMEM>>>(o116, w1, b1, nullptr, f16, MM, FF, CC);
    gemm_mma<0,1,0><<<gC, 256, GEMM_SMEM>>>(f16, w2, b2, tmp, nullptr, MM, CC, FF);
    add_ln<<<MM, 256>>>(out1, tmp, ln2_g, ln2_b, out2, o216);

    // --- final pointwise conv: out = out2 @ Wc^T + bc ---
    gemm_mma<0,1,0><<<gC, 256, GEMM_SMEM>>>(o216, wc, bc, out, nullptr, MM, CC, CC);
}

// round 14
// speedup vs baseline: 1.1947x; 1.1947x over previous
#include <cuda_runtime.h>
#include <cuda_fp16.h>
#include <math.h>
#include <stdint.h>

// Problem dims (fixed)
#define BB   2
#define TT   2048
#define CC   1024
#define EE   1024
#define HH   16
#define HS   64
#define FF   4096
#define MM   (BB*TT)   // 4096 rows
#define QKV  (3*EE)    // 3072

// ======================= scratch (static device globals) ===================
__device__ float g_out1[MM*CC];
__device__ float g_out2[MM*CC];
__device__ float g_bqkv[QKV];

__device__ __half g_tmph[MM*CC];      // fp16 GEMM outputs feeding add_ln
__device__ __half g_x16 [MM*CC];
__device__ __half g_qkv [MM*QKV];
__device__ __half g_a16 [MM*EE];
__device__ __half g_o116[MM*CC];
__device__ __half g_f16 [MM*FF];
__device__ __half g_o216[MM*CC];
// transposed weights: [N, K] fp16
__device__ __half g_wqkv[QKV*CC];
__device__ __half g_wo  [CC*EE];
__device__ __half g_w1  [FF*CC];
__device__ __half g_w2  [CC*FF];
__device__ __half g_wc  [CC*CC];

// ======================= small PTX helpers =================================
__device__ __forceinline__ uint32_t smem_u32(const void* p) {
    uint32_t a;
    asm("{ .reg .u64 t; cvta.to.shared.u64 t, %1; cvt.u32.u64 %0, t; }"
        : "=r"(a) : "l"(p));
    return a;
}
__device__ __forceinline__ void cp16(uint32_t saddr, const void* gaddr) {
    asm volatile("cp.async.cg.shared.global [%0], [%1], 16;"
                 :: "r"(saddr), "l"(gaddr) : "memory");
}
#define CP_COMMIT() asm volatile("cp.async.commit_group;" ::: "memory")
#define CP_WAIT(n)  asm volatile("cp.async.wait_group %0;" :: "n"(n) : "memory")

__device__ __forceinline__ void ldsm_x4(uint32_t r[4], uint32_t addr) {
    asm volatile("ldmatrix.sync.aligned.m8n8.x4.shared.b16 {%0,%1,%2,%3}, [%4];"
                 : "=r"(r[0]), "=r"(r[1]), "=r"(r[2]), "=r"(r[3]) : "r"(addr));
}
__device__ __forceinline__ void ldsm_x4_t(uint32_t r[4], uint32_t addr) {
    asm volatile("ldmatrix.sync.aligned.m8n8.x4.trans.shared.b16 {%0,%1,%2,%3}, [%4];"
                 : "=r"(r[0]), "=r"(r[1]), "=r"(r[2]), "=r"(r[3]) : "r"(addr));
}
__device__ __forceinline__ void mma16816(float c[4],
    uint32_t a0, uint32_t a1, uint32_t a2, uint32_t a3, uint32_t b0, uint32_t b1)
{
    asm volatile(
        "mma.sync.aligned.m16n8k16.row.col.f32.f16.f16.f32 "
        "{%0,%1,%2,%3}, {%4,%5,%6,%7}, {%8,%9}, {%0,%1,%2,%3};"
        : "+f"(c[0]), "+f"(c[1]), "+f"(c[2]), "+f"(c[3])
        : "r"(a0), "r"(a1), "r"(a2), "r"(a3), "r"(b0), "r"(b1));
}
__device__ __forceinline__ uint32_t packh(__half a, __half b) {
    __half2 t = __halves2half2(a, b);
    return *(uint32_t*)&t;
}
__device__ __forceinline__ float ex2(float x) {
    float y;
    asm("ex2.approx.f32 %0, %1;" : "=f"(y) : "f"(x));
    return y;
}

// ======================= fused prep kernel =================================
__device__ __forceinline__ void transpose_block(
    const float* __restrict__ W, __half* __restrict__ T,
    int K, int N, int bb, float (*t)[33])
{
    const int nb = N >> 5;
    const int bx = bb % nb, by = bb / nb;
    const int n0 = bx * 32, k0 = by * 32;
    const int tx = threadIdx.x & 31, ty = threadIdx.x >> 5;
    #pragma unroll
    for (int s = 0; s < 32; s += 8)
        t[ty + s][tx] = W[(size_t)(k0 + ty + s) * N + n0 + tx];
    __syncthreads();
    #pragma unroll
    for (int s = 0; s < 32; s += 8)
        T[(size_t)(n0 + ty + s) * K + k0 + tx] = __float2half_rn(t[tx][ty + s]);
}
__device__ __forceinline__ void convert_block(
    const float* __restrict__ in, __half* __restrict__ o, int bb)
{
    const int idx = bb * 1024 + threadIdx.x * 4;
    float4 v = *(const float4*)(in + idx);
    *(__half2*)(o + idx)     = __halves2half2(__float2half_rn(v.x), __float2half_rn(v.y));
    *(__half2*)(o + idx + 2) = __halves2half2(__float2half_rn(v.z), __float2half_rn(v.w));
}

#define PREP_GRID 17411

__global__ __launch_bounds__(256) void prep_all(
    const float* __restrict__ Wq, const float* __restrict__ Wk,
    const float* __restrict__ Wv, const float* __restrict__ Wo,
    const float* __restrict__ W1, const float* __restrict__ W2,
    const float* __restrict__ Wc, const float* __restrict__ x,
    const float* __restrict__ bq, const float* __restrict__ bk,
    const float* __restrict__ bv,
    __half* __restrict__ wqkv, __half* __restrict__ wo,
    __half* __restrict__ w1,   __half* __restrict__ w2,
    __half* __restrict__ wc,   __half* __restrict__ x16,
    float* __restrict__ bqkv)
{
    __shared__ float t[32][33];
    const int b = blockIdx.x;
    if (b < 3072) {
        const int seg = b >> 10, bb = b & 1023;
        const float* W = (seg == 0) ? Wq : (seg == 1) ? Wk : Wv;
        transpose_block(W, wqkv + (size_t)seg * EE * CC, CC, EE, bb, t);
    } else if (b < 4096) {
        transpose_block(Wo, wo, EE, CC, b - 3072, t);
    } else if (b < 8192) {
        transpose_block(W1, w1, CC, FF, b - 4096, t);
    } else if (b < 12288) {
        transpose_block(W2, w2, FF, CC, b - 8192, t);
    } else if (b < 13312) {
        convert_block(Wc, wc, b - 12288);
    } else if (b < 17408) {
        convert_block(x, x16, b - 13312);
    } else {
        const int bb = b - 17408;
        const float* src = (bb == 0) ? bq : (bb == 1) ? bk : bv;
        ((float4*)(bqkv + bb * EE))[threadIdx.x] = ((const float4*)src)[threadIdx.x];
    }
}

// ======================= swizzle (128B rows, 8 x 16B chunks) ===============
__device__ __forceinline__ uint32_t sw8(int row, int ch) {
    return (uint32_t)(row * 128 + ((ch ^ (row & 7)) << 4));
}

// ======================= HMMA fp16 GEMM (R11: BK=64, 2-stage, 1 sync) ======
#define STAGE_BYTES 32768
#define ARR_A 0
#define ARR_B 16384
#define GEMM_SMEM (2*STAGE_BYTES)

template<int GELU, int WF32, int WH>
__global__ __launch_bounds__(256, 2) void gemm_mma(
    const __half* __restrict__ A, const __half* __restrict__ Bw,
    const float* __restrict__ bias,
    float* __restrict__ Cf, __half* __restrict__ Ch,
    int M, int N, int K)
{
    extern __shared__ char sm[];
    const uint32_t su = smem_u32(sm);

    const int tid  = threadIdx.x;
    const int wid  = tid >> 5;
    const int lane = tid & 31;
    const int m0 = blockIdx.y * 128;
    const int n0 = blockIdx.x * 128;
    const int wm0 = (wid & 1) * 64;
    const int wn0 = (wid >> 1) * 32;

    float acc[4][4][4];
    #pragma unroll
    for (int mt = 0; mt < 4; mt++)
        #pragma unroll
        for (int nt = 0; nt < 4; nt++)
            #pragma unroll
            for (int i = 0; i < 4; i++) acc[mt][nt][i] = 0.f;

    const int nCh = K >> 6;   // 64-wide chunks

    auto issue = [&](int c, int stg) {
        const uint32_t sbase = su + stg * STAGE_BYTES;
        #pragma unroll
        for (int i = 0; i < 4; i++) {
            const int vec = tid + i * 256;
            const int row = vec >> 3;
            const int ch  = vec & 7;
            const uint32_t so = sw8(row, ch);
            const size_t gA = ((size_t)(m0 + row) * K + c * 64 + ch * 8) * 2;
            const size_t gB = ((size_t)(n0 + row) * K + c * 64 + ch * 8) * 2;
            cp16(sbase + ARR_A + so, (const char*)A  + gA);
            cp16(sbase + ARR_B + so, (const char*)Bw + gB);
        }
    };

    issue(0, 0);
    CP_COMMIT();

    const int grp = lane >> 3, wi = lane & 7;

    for (int c = 0; c < nCh; c++) {
        const int stg = c & 1;
        CP_WAIT(0);
        __syncthreads();
        if (c + 1 < nCh) {
            issue(c + 1, stg ^ 1);
            CP_COMMIT();
        }

        const uint32_t sbase = su + stg * STAGE_BYTES;

        #pragma unroll
        for (int ks = 0; ks < 4; ks++) {
            uint32_t bfr[4][2];
            const int brow_base = wn0 + wi + ((grp >> 1) << 3);
            const int bchunk = ks * 2 + (grp & 1);
            #pragma unroll
            for (int bt = 0; bt < 2; bt++) {
                uint32_t r4[4];
                const int br = brow_base + bt * 16;
                ldsm_x4(r4, sbase + ARR_B + sw8(br, bchunk));
                bfr[bt*2][0]   = r4[0]; bfr[bt*2][1]   = r4[1];
                bfr[bt*2+1][0] = r4[2]; bfr[bt*2+1][1] = r4[3];
            }

            const int arow = wm0 + (lane & 15);
            const int achunk = ks * 2 + (lane >> 4);
            uint32_t a[4][4];
            #pragma unroll
            for (int mt = 0; mt < 4; mt++)
                ldsm_x4(a[mt], sbase + ARR_A + sw8(arow + mt * 16, achunk));
            #pragma unroll
            for (int mt = 0; mt < 4; mt++)
                #pragma unroll
                for (int nt = 0; nt < 4; nt++)
                    mma16816(acc[mt][nt], a[mt][0], a[mt][1], a[mt][2], a[mt][3],
                             bfr[nt][0], bfr[nt][1]);
        }
    }

    const int er = lane >> 2;
    const int ec = (lane & 3) * 2;
    #pragma unroll
    for (int mt = 0; mt < 4; mt++) {
        #pragma unroll
        for (int nt = 0; nt < 4; nt++) {
            const int col = n0 + wn0 + nt * 8 + ec;
            const float b0 = bias[col], b1 = bias[col + 1];
            const int rA = m0 + wm0 + mt * 16 + er;
            const int rB = rA + 8;
            float v00 = acc[mt][nt][0] + b0;
            float v01 = acc[mt][nt][1] + b1;
            float v10 = acc[mt][nt][2] + b0;
            float v11 = acc[mt][nt][3] + b1;
            if (GELU) {
                v00 = 0.5f * v00 * (1.0f + erff(v00 * 0.70710678118654752f));
                v01 = 0.5f * v01 * (1.0f + erff(v01 * 0.70710678118654752f));
                v10 = 0.5f * v10 * (1.0f + erff(v10 * 0.70710678118654752f));
                v11 = 0.5f * v11 * (1.0f + erff(v11 * 0.70710678118654752f));
            }
            if (WF32) {
                *(float2*)(Cf + (size_t)rA * N + col) = make_float2(v00, v01);
                *(float2*)(Cf + (size_t)rB * N + col) = make_float2(v10, v11);
            }
            if (WH) {
                *(__half2*)(Ch + (size_t)rA * N + col) =
                    __halves2half2(__float2half_rn(v00), __float2half_rn(v01));
                *(__half2*)(Ch + (size_t)rB * N + col) =
                    __halves2half2(__float2half_rn(v10), __float2half_rn(v11));
            }
        }
    }
}

// ======================= tensor-core flash attention (R11) =================
#define ASM_Q   0
#define KBUF(b) (16384 + (b) * 16384)
#define VBUF(b) (16384 + (b) * 16384 + 8192)
#define ATTN_SMEM 49152
#define NSCH (TT/64)   // 32
#define SCALE2 0.18033688011112042f   // 0.125 * log2(e)

__global__ void __launch_bounds__(256, 2) attn_mma(
    const __half* __restrict__ QKVp, __half* __restrict__ O)
{
    extern __shared__ char sm[];
    const uint32_t su = smem_u32(sm);

    const int tid  = threadIdx.x;
    const int wid  = tid >> 5;
    const int lane = tid & 31;
    const int q0 = blockIdx.x * 128;
    const int bh = blockIdx.y;
    const int b  = bh >> 4;
    const int h  = bh & 15;
    const size_t mrow0 = (size_t)b * TT;
    const size_t qbase = (mrow0 + q0) * QKV + h * HS;

    const int wm  = wid * 16;
    const int grp = lane >> 3, wi = lane & 7;

    #pragma unroll
    for (int i = 0; i < 4; i++) {
        int vec = tid + i * 256;
        int row = vec >> 3, ch = vec & 7;
        const size_t g = (qbase + (size_t)row * QKV + ch * 8) * 2;
        cp16(su + ASM_Q + sw8(row, ch), (const char*)QKVp + g);
    }
    CP_COMMIT();

    auto issueKV = [&](int s, int stg) {
        const size_t kb = ((mrow0 + (size_t)s * 64) * QKV + EE + h * HS) * 2;
        #pragma unroll
        for (int i = 0; i < 2; i++) {
            int vec = tid + i * 256;
            int row = vec >> 3, ch = vec & 7;
            const size_t off = ((size_t)row * QKV + ch * 8) * 2;
            cp16(su + KBUF(stg) + sw8(row, ch), (const char*)QKVp + kb + off);
            cp16(su + VBUF(stg) + sw8(row, ch), (const char*)QKVp + kb + EE*2 + off);
        }
    };
    issueKV(0, 0);
    CP_COMMIT();

    float m0 = -1e30f, m1 = -1e30f, l0 = 0.f, l1 = 0.f;
    float oacc[8][4];
    #pragma unroll
    for (int nt = 0; nt < 8; nt++)
        #pragma unroll
        for (int i = 0; i < 4; i++) oacc[nt][i] = 0.f;

    for (int s = 0; s < NSCH; s++) {
        const int stg = s & 1;
        CP_WAIT(0);
        __syncthreads();
        if (s + 1 < NSCH) {
            issueKV(s + 1, stg ^ 1);
            CP_COMMIT();
        }

        const uint32_t kbase = su + KBUF(stg);
        const uint32_t vbase = su + VBUF(stg);

        float sacc[8][4];
        #pragma unroll
        for (int nt = 0; nt < 8; nt++)
            #pragma unroll
            for (int i = 0; i < 4; i++) sacc[nt][i] = 0.f;

        #pragma unroll
        for (int ks = 0; ks < 4; ks++) {
            const int arow = wm + (lane & 15);
            const int achunk = ks * 2 + (lane >> 4);
            uint32_t qa[4];
            ldsm_x4(qa, su + ASM_Q + sw8(arow, achunk));

            uint32_t kf[8][2];
            #pragma unroll
            for (int bt = 0; bt < 4; bt++) {
                const int br = wi + ((grp >> 1) << 3) + bt * 16;
                const int bch = ks * 2 + (grp & 1);
                uint32_t r4[4];
                ldsm_x4(r4, kbase + sw8(br, bch));
                kf[bt*2][0] = r4[0]; kf[bt*2][1] = r4[1];
                kf[bt*2+1][0] = r4[2]; kf[bt*2+1][1] = r4[3];
            }
            #pragma unroll
            for (int nt = 0; nt < 8; nt++)
                mma16816(sacc[nt], qa[0], qa[1], qa[2], qa[3], kf[nt][0], kf[nt][1]);
        }

        float rmax0 = -1e30f, rmax1 = -1e30f;
        #pragma unroll
        for (int nt = 0; nt < 8; nt++) {
            #pragma unroll
            for (int i = 0; i < 4; i++) sacc[nt][i] *= SCALE2;
            rmax0 = fmaxf(rmax0, fmaxf(sacc[nt][0], sacc[nt][1]));
            rmax1 = fmaxf(rmax1, fmaxf(sacc[nt][2], sacc[nt][3]));
        }
        #pragma unroll
        for (int msk = 1; msk < 4; msk <<= 1) {
            rmax0 = fmaxf(rmax0, __shfl_xor_sync(0xffffffffu, rmax0, msk));
            rmax1 = fmaxf(rmax1, __shfl_xor_sync(0xffffffffu, rmax1, msk));
        }
        const float nm0 = fmaxf(m0, rmax0);
        const float nm1 = fmaxf(m1, rmax1);
        const float corr0 = ex2(m0 - nm0);
        const float corr1 = ex2(m1 - nm1);

        uint32_t pa[4][4];
        float sum0 = 0.f, sum1 = 0.f;
        #pragma unroll
        for (int nt = 0; nt < 8; nt++) {
            float p0 = ex2(sacc[nt][0] - nm0);
            float p1 = ex2(sacc[nt][1] - nm0);
            float p2 = ex2(sacc[nt][2] - nm1);
            float p3 = ex2(sacc[nt][3] - nm1);
            sum0 += p0 + p1;
            sum1 += p2 + p3;
            const int kt = nt >> 1, hf = nt & 1;
            pa[kt][hf*2]   = packh(__float2half_rn(p0), __float2half_rn(p1));
            pa[kt][hf*2+1] = packh(__float2half_rn(p2), __float2half_rn(p3));
        }
        #pragma unroll
        for (int msk = 1; msk < 4; msk <<= 1) {
            sum0 += __shfl_xor_sync(0xffffffffu, sum0, msk);
            sum1 += __shfl_xor_sync(0xffffffffu, sum1, msk);
        }
        l0 = l0 * corr0 + sum0;
        l1 = l1 * corr1 + sum1;
        m0 = nm0; m1 = nm1;
        #pragma unroll
        for (int nt = 0; nt < 8; nt++) {
            oacc[nt][0] *= corr0; oacc[nt][1] *= corr0;
            oacc[nt][2] *= corr1; oacc[nt][3] *= corr1;
        }

        #pragma unroll
        for (int ks = 0; ks < 4; ks++) {
            uint32_t vf[8][2];
            #pragma unroll
            for (int bt = 0; bt < 4; bt++) {
                const int key_row = ks * 16 + (grp & 1) * 8 + wi;
                const int dim_ch  = bt * 2 + (grp >> 1);
                uint32_t r4[4];
                ldsm_x4_t(r4, vbase + sw8(key_row, dim_ch));
                vf[bt*2][0] = r4[0]; vf[bt*2][1] = r4[1];
                vf[bt*2+1][0] = r4[2]; vf[bt*2+1][1] = r4[3];
            }
            #pragma unroll
            for (int nt = 0; nt < 8; nt++)
                mma16816(oacc[nt], pa[ks][0], pa[ks][1], pa[ks][2], pa[ks][3],
                         vf[nt][0], vf[nt][1]);
        }
    }

    const float inv0 = 1.0f / l0;
    const float inv1 = 1.0f / l1;
    const int r = lane >> 2;
    const int qcol = 2 * (lane & 3);
    const size_t row0 = (mrow0 + q0 + wm + r) * EE + h * HS;
    const size_t row1 = row0 + (size_t)8 * EE;
    #pragma unroll
    for (int nt = 0; nt < 8; nt++) {
        const int col = nt * 8 + qcol;
        *(__half2*)(O + row0 + col) = __halves2half2(
            __float2half_rn(oacc[nt][0] * inv0), __float2half_rn(oacc[nt][1] * inv0));
        *(__half2*)(O + row1 + col) = __halves2half2(
            __float2half_rn(oacc[nt][2] * inv1), __float2half_rn(oacc[nt][3] * inv1));
    }
}

// ======================= residual add + LayerNorm (fp16 delta) =============
__global__ __launch_bounds__(256) void add_ln(
    const float* __restrict__ a, const __half* __restrict__ bsrc,
    const float* __restrict__ g, const float* __restrict__ beta,
    float* __restrict__ out, __half* __restrict__ oh)
{
    const int row = blockIdx.x;
    const int tid = threadIdx.x;
    const float4 av = ((const float4*)(a + (size_t)row * CC))[tid];
    const __half2 h01 = ((const __half2*)(bsrc + (size_t)row * CC))[tid*2];
    const __half2 h23 = ((const __half2*)(bsrc + (size_t)row * CC))[tid*2 + 1];
    const float2 b01 = __half22float2(h01);
    const float2 b23 = __half22float2(h23);
    float4 v = make_float4(av.x + b01.x, av.y + b01.y, av.z + b23.x, av.w + b23.y);

    float s  = v.x + v.y + v.z + v.w;
    float ss = v.x*v.x + v.y*v.y + v.z*v.z + v.w*v.w;
    #pragma unroll
    for (int msk = 16; msk; msk >>= 1) {
        s  += __shfl_xor_sync(0xffffffffu, s,  msk);
        ss += __shfl_xor_sync(0xffffffffu, ss, msk);
    }
    __shared__ float ws[8], wss[8];
    __shared__ float mu_s, rstd_s;
    const int w = tid >> 5, lane = tid & 31;
    if (lane == 0) { ws[w] = s; wss[w] = ss; }
    __syncthreads();
    if (tid == 0) {
        float S = 0.f, SS = 0.f;
        #pragma unroll
        for (int i = 0; i < 8; i++) { S += ws[i]; SS += wss[i]; }
        float mu  = S * (1.0f / CC);
        float var = SS * (1.0f / CC) - mu * mu;
        mu_s   = mu;
        rstd_s = rsqrtf(var + 1e-5f);
    }
    __syncthreads();
    const float mu = mu_s, rstd = rstd_s;
    const float4 gv = ((const float4*)g)[tid];
    const float4 bv2 = ((const float4*)beta)[tid];
    float4 ov;
    ov.x = (v.x - mu) * rstd * gv.x + bv2.x;
    ov.y = (v.y - mu) * rstd * gv.y + bv2.y;
    ov.z = (v.z - mu) * rstd * gv.z + bv2.z;
    ov.w = (v.w - mu) * rstd * gv.w + bv2.w;
    ((float4*)(out + (size_t)row * CC))[tid] = ov;

    if (oh) {
        size_t o = (size_t)row * CC + tid * 4;
        *(__half2*)(oh + o)     = __halves2half2(__float2half_rn(ov.x), __float2half_rn(ov.y));
        *(__half2*)(oh + o + 2) = __halves2half2(__float2half_rn(ov.z), __float2half_rn(ov.w));
    }
}

// ======================= launch ============================================
extern "C" void kernel_launch(void* const* d_in, const int* in_sizes, int n_in,
                              void* d_out, int out_size)
{
    const float* x     = (const float*)d_in[0];
    const float* Wq    = (const float*)d_in[1];
    const float* bq    = (const float*)d_in[2];
    const float* Wk    = (const float*)d_in[3];
    const float* bk    = (const float*)d_in[4];
    const float* Wv    = (const float*)d_in[5];
    const float* bv    = (const float*)d_in[6];
    const float* Wo    = (const float*)d_in[7];
    const float* bo    = (const float*)d_in[8];
    const float* ln1_g = (const float*)d_in[9];
    const float* ln1_b = (const float*)d_in[10];
    const float* W1    = (const float*)d_in[11];
    const float* b1    = (const float*)d_in[12];
    const float* W2    = (const float*)d_in[13];
    const float* b2    = (const float*)d_in[14];
    const float* ln2_g = (const float*)d_in[15];
    const float* ln2_b = (const float*)d_in[16];
    const float* Wc    = (const float*)d_in[17];
    const float* bc    = (const float*)d_in[18];
    float* out = (float*)d_out;

    float *out1, *out2, *bqkv;
    cudaGetSymbolAddress((void**)&out1, g_out1);
    cudaGetSymbolAddress((void**)&out2, g_out2);
    cudaGetSymbolAddress((void**)&bqkv, g_bqkv);

    __half *tmph,*x16,*qkv,*a16,*o116,*f16,*o216,*wqkv,*wo,*w1,*w2,*wc;
    cudaGetSymbolAddress((void**)&tmph, g_tmph);
    cudaGetSymbolAddress((void**)&x16,  g_x16);
    cudaGetSymbolAddress((void**)&qkv,  g_qkv);
    cudaGetSymbolAddress((void**)&a16,  g_a16);
    cudaGetSymbolAddress((void**)&o116, g_o116);
    cudaGetSymbolAddress((void**)&f16,  g_f16);
    cudaGetSymbolAddress((void**)&o216, g_o216);
    cudaGetSymbolAddress((void**)&wqkv, g_wqkv);
    cudaGetSymbolAddress((void**)&wo,   g_wo);
    cudaGetSymbolAddress((void**)&w1,   g_w1);
    cudaGetSymbolAddress((void**)&w2,   g_w2);
    cudaGetSymbolAddress((void**)&wc,   g_wc);

    cudaFuncSetAttribute(gemm_mma<0,1,0>,
                         cudaFuncAttributeMaxDynamicSharedMemorySize, GEMM_SMEM);
    cudaFuncSetAttribute(gemm_mma<0,0,1>,
                         cudaFuncAttributeMaxDynamicSharedMemorySize, GEMM_SMEM);
    cudaFuncSetAttribute(gemm_mma<1,0,1>,
                         cudaFuncAttributeMaxDynamicSharedMemorySize, GEMM_SMEM);
    cudaFuncSetAttribute(attn_mma,
                         cudaFuncAttributeMaxDynamicSharedMemorySize, ATTN_SMEM);

    // --- all prep in ONE launch ---
    prep_all<<<PREP_GRID, 256>>>(Wq, Wk, Wv, Wo, W1, W2, Wc, x, bq, bk, bv,
                                 wqkv, wo, w1, w2, wc, x16, bqkv);

    // --- fused QKV projection (N = 3072) ---
    const dim3 gQKV(QKV/128, MM/128);
    const dim3 gC(CC/128, MM/128);
    const dim3 gF(FF/128, MM/128);
    gemm_mma<0,0,1><<<gQKV, 256, GEMM_SMEM>>>(x16, wqkv, bqkv, nullptr, qkv, MM, QKV, CC);

    // --- attention ---
    attn_mma<<<dim3(TT/128, BB*HH), 256, ATTN_SMEM>>>(qkv, a16);

    // --- output projection (fp16 out) + residual + LN1 ---
    gemm_mma<0,0,1><<<gC, 256, GEMM_SMEM>>>(a16, wo, bo, nullptr, tmph, MM, CC, EE);
    add_ln<<<MM, 256>>>(x, tmph, ln1_g, ln1_b, out1, o116);

    // --- FFN ---
    gemm_mma<1,0,1><<<gF, 256, GEMM_SMEM>>>(o116, w1, b1, nullptr, f16, MM, FF, CC);
    gemm_mma<0,0,1><<<gC, 256, GEMM_SMEM>>>(f16, w2, b2, nullptr, tmph, MM, CC, FF);
    add_ln<<<MM, 256>>>(out1, tmph, ln2_g, ln2_b, out2, o216);

    // --- final pointwise conv: out = out2 @ Wc^T + bc ---
    gemm_mma<0,1,0><<<gC, 256, GEMM_SMEM>>>(o216, wc, bc, out, nullptr, MM, CC, CC);
}

// round 15
// speedup vs baseline: 1.2006x; 1.0049x over previous
#include <cuda_runtime.h>
#include <cuda_fp16.h>
#include <math.h>
#include <stdint.h>

// Problem dims (fixed)
#define BB   2
#define TT   2048
#define CC   1024
#define EE   1024
#define HH   16
#define HS   64
#define FF   4096
#define MM   (BB*TT)   // 4096 rows
#define QKV  (3*EE)    // 3072

// ======================= scratch (static device globals) ===================
__device__ float g_bqkv[QKV];

__device__ __half g_tmph[MM*CC];      // fp16 GEMM outputs feeding add_ln
__device__ __half g_x16 [MM*CC];
__device__ __half g_qkv [MM*QKV];
__device__ __half g_a16 [MM*EE];
__device__ __half g_o116[MM*CC];
__device__ __half g_f16 [MM*FF];
__device__ __half g_o216[MM*CC];
// transposed weights: [N, K] fp16
__device__ __half g_wqkv[QKV*CC];
__device__ __half g_wo  [CC*EE];
__device__ __half g_w1  [FF*CC];
__device__ __half g_w2  [CC*FF];
__device__ __half g_wc  [CC*CC];

// ======================= small PTX helpers =================================
__device__ __forceinline__ uint32_t smem_u32(const void* p) {
    uint32_t a;
    asm("{ .reg .u64 t; cvta.to.shared.u64 t, %1; cvt.u32.u64 %0, t; }"
        : "=r"(a) : "l"(p));
    return a;
}
__device__ __forceinline__ void cp16(uint32_t saddr, const void* gaddr) {
    asm volatile("cp.async.cg.shared.global [%0], [%1], 16;"
                 :: "r"(saddr), "l"(gaddr) : "memory");
}
#define CP_COMMIT() asm volatile("cp.async.commit_group;" ::: "memory")
#define CP_WAIT(n)  asm volatile("cp.async.wait_group %0;" :: "n"(n) : "memory")

__device__ __forceinline__ void ldsm_x4(uint32_t r[4], uint32_t addr) {
    asm volatile("ldmatrix.sync.aligned.m8n8.x4.shared.b16 {%0,%1,%2,%3}, [%4];"
                 : "=r"(r[0]), "=r"(r[1]), "=r"(r[2]), "=r"(r[3]) : "r"(addr));
}
__device__ __forceinline__ void ldsm_x4_t(uint32_t r[4], uint32_t addr) {
    asm volatile("ldmatrix.sync.aligned.m8n8.x4.trans.shared.b16 {%0,%1,%2,%3}, [%4];"
                 : "=r"(r[0]), "=r"(r[1]), "=r"(r[2]), "=r"(r[3]) : "r"(addr));
}
__device__ __forceinline__ void mma16816(float c[4],
    uint32_t a0, uint32_t a1, uint32_t a2, uint32_t a3, uint32_t b0, uint32_t b1)
{
    asm volatile(
        "mma.sync.aligned.m16n8k16.row.col.f32.f16.f16.f32 "
        "{%0,%1,%2,%3}, {%4,%5,%6,%7}, {%8,%9}, {%0,%1,%2,%3};"
        : "+f"(c[0]), "+f"(c[1]), "+f"(c[2]), "+f"(c[3])
        : "r"(a0), "r"(a1), "r"(a2), "r"(a3), "r"(b0), "r"(b1));
}
__device__ __forceinline__ uint32_t packh(__half a, __half b) {
    __half2 t = __halves2half2(a, b);
    return *(uint32_t*)&t;
}
__device__ __forceinline__ float ex2(float x) {
    float y;
    asm("ex2.approx.f32 %0, %1;" : "=f"(y) : "f"(x));
    return y;
}

// ======================= fused prep kernel =================================
__device__ __forceinline__ void transpose_block(
    const float* __restrict__ W, __half* __restrict__ T,
    int K, int N, int bb, float (*t)[33])
{
    const int nb = N >> 5;
    const int bx = bb % nb, by = bb / nb;
    const int n0 = bx * 32, k0 = by * 32;
    const int tx = threadIdx.x & 31, ty = threadIdx.x >> 5;
    #pragma unroll
    for (int s = 0; s < 32; s += 8)
        t[ty + s][tx] = W[(size_t)(k0 + ty + s) * N + n0 + tx];
    __syncthreads();
    #pragma unroll
    for (int s = 0; s < 32; s += 8)
        T[(size_t)(n0 + ty + s) * K + k0 + tx] = __float2half_rn(t[tx][ty + s]);
}
__device__ __forceinline__ void convert_block(
    const float* __restrict__ in, __half* __restrict__ o, int bb)
{
    const int idx = bb * 1024 + threadIdx.x * 4;
    float4 v = *(const float4*)(in + idx);
    *(__half2*)(o + idx)     = __halves2half2(__float2half_rn(v.x), __float2half_rn(v.y));
    *(__half2*)(o + idx + 2) = __halves2half2(__float2half_rn(v.z), __float2half_rn(v.w));
}

#define PREP_GRID 17411

__global__ __launch_bounds__(256) void prep_all(
    const float* __restrict__ Wq, const float* __restrict__ Wk,
    const float* __restrict__ Wv, const float* __restrict__ Wo,
    const float* __restrict__ W1, const float* __restrict__ W2,
    const float* __restrict__ Wc, const float* __restrict__ x,
    const float* __restrict__ bq, const float* __restrict__ bk,
    const float* __restrict__ bv,
    __half* __restrict__ wqkv, __half* __restrict__ wo,
    __half* __restrict__ w1,   __half* __restrict__ w2,
    __half* __restrict__ wc,   __half* __restrict__ x16,
    float* __restrict__ bqkv)
{
    __shared__ float t[32][33];
    const int b = blockIdx.x;
    if (b < 3072) {
        const int seg = b >> 10, bb = b & 1023;
        const float* W = (seg == 0) ? Wq : (seg == 1) ? Wk : Wv;
        transpose_block(W, wqkv + (size_t)seg * EE * CC, CC, EE, bb, t);
    } else if (b < 4096) {
        transpose_block(Wo, wo, EE, CC, b - 3072, t);
    } else if (b < 8192) {
        transpose_block(W1, w1, CC, FF, b - 4096, t);
    } else if (b < 12288) {
        transpose_block(W2, w2, FF, CC, b - 8192, t);
    } else if (b < 13312) {
        convert_block(Wc, wc, b - 12288);
    } else if (b < 17408) {
        convert_block(x, x16, b - 13312);
    } else {
        const int bb = b - 17408;
        const float* src = (bb == 0) ? bq : (bb == 1) ? bk : bv;
        ((float4*)(bqkv + bb * EE))[threadIdx.x] = ((const float4*)src)[threadIdx.x];
    }
}

// ======================= swizzle (128B rows, 8 x 16B chunks) ===============
__device__ __forceinline__ uint32_t sw8(int row, int ch) {
    return (uint32_t)(row * 128 + ((ch ^ (row & 7)) << 4));
}

// ======================= HMMA fp16 GEMM (R11: BK=64, 2-stage, 1 sync) ======
#define STAGE_BYTES 32768
#define ARR_A 0
#define ARR_B 16384
#define GEMM_SMEM (2*STAGE_BYTES)

template<int GELU, int WF32, int WH>
__global__ __launch_bounds__(256, 2) void gemm_mma(
    const __half* __restrict__ A, const __half* __restrict__ Bw,
    const float* __restrict__ bias,
    float* __restrict__ Cf, __half* __restrict__ Ch,
    int M, int N, int K)
{
    extern __shared__ char sm[];
    const uint32_t su = smem_u32(sm);

    const int tid  = threadIdx.x;
    const int wid  = tid >> 5;
    const int lane = tid & 31;
    const int m0 = blockIdx.y * 128;
    const int n0 = blockIdx.x * 128;
    const int wm0 = (wid & 1) * 64;
    const int wn0 = (wid >> 1) * 32;

    float acc[4][4][4];
    #pragma unroll
    for (int mt = 0; mt < 4; mt++)
        #pragma unroll
        for (int nt = 0; nt < 4; nt++)
            #pragma unroll
            for (int i = 0; i < 4; i++) acc[mt][nt][i] = 0.f;

    const int nCh = K >> 6;   // 64-wide chunks

    auto issue = [&](int c, int stg) {
        const uint32_t sbase = su + stg * STAGE_BYTES;
        #pragma unroll
        for (int i = 0; i < 4; i++) {
            const int vec = tid + i * 256;
            const int row = vec >> 3;
            const int ch  = vec & 7;
            const uint32_t so = sw8(row, ch);
            const size_t gA = ((size_t)(m0 + row) * K + c * 64 + ch * 8) * 2;
            const size_t gB = ((size_t)(n0 + row) * K + c * 64 + ch * 8) * 2;
            cp16(sbase + ARR_A + so, (const char*)A  + gA);
            cp16(sbase + ARR_B + so, (const char*)Bw + gB);
        }
    };

    issue(0, 0);
    CP_COMMIT();

    const int grp = lane >> 3, wi = lane & 7;

    for (int c = 0; c < nCh; c++) {
        const int stg = c & 1;
        CP_WAIT(0);
        __syncthreads();
        if (c + 1 < nCh) {
            issue(c + 1, stg ^ 1);
            CP_COMMIT();
        }

        const uint32_t sbase = su + stg * STAGE_BYTES;

        #pragma unroll
        for (int ks = 0; ks < 4; ks++) {
            uint32_t bfr[4][2];
            const int brow_base = wn0 + wi + ((grp >> 1) << 3);
            const int bchunk = ks * 2 + (grp & 1);
            #pragma unroll
            for (int bt = 0; bt < 2; bt++) {
                uint32_t r4[4];
                const int br = brow_base + bt * 16;
                ldsm_x4(r4, sbase + ARR_B + sw8(br, bchunk));
                bfr[bt*2][0]   = r4[0]; bfr[bt*2][1]   = r4[1];
                bfr[bt*2+1][0] = r4[2]; bfr[bt*2+1][1] = r4[3];
            }

            const int arow = wm0 + (lane & 15);
            const int achunk = ks * 2 + (lane >> 4);
            uint32_t a[4][4];
            #pragma unroll
            for (int mt = 0; mt < 4; mt++)
                ldsm_x4(a[mt], sbase + ARR_A + sw8(arow + mt * 16, achunk));
            #pragma unroll
            for (int mt = 0; mt < 4; mt++)
                #pragma unroll
                for (int nt = 0; nt < 4; nt++)
                    mma16816(acc[mt][nt], a[mt][0], a[mt][1], a[mt][2], a[mt][3],
                             bfr[nt][0], bfr[nt][1]);
        }
    }

    const int er = lane >> 2;
    const int ec = (lane & 3) * 2;
    #pragma unroll
    for (int mt = 0; mt < 4; mt++) {
        #pragma unroll
        for (int nt = 0; nt < 4; nt++) {
            const int col = n0 + wn0 + nt * 8 + ec;
            const float b0 = bias[col], b1 = bias[col + 1];
            const int rA = m0 + wm0 + mt * 16 + er;
            const int rB = rA + 8;
            float v00 = acc[mt][nt][0] + b0;
            float v01 = acc[mt][nt][1] + b1;
            float v10 = acc[mt][nt][2] + b0;
            float v11 = acc[mt][nt][3] + b1;
            if (GELU) {
                v00 = 0.5f * v00 * (1.0f + erff(v00 * 0.70710678118654752f));
                v01 = 0.5f * v01 * (1.0f + erff(v01 * 0.70710678118654752f));
                v10 = 0.5f * v10 * (1.0f + erff(v10 * 0.70710678118654752f));
                v11 = 0.5f * v11 * (1.0f + erff(v11 * 0.70710678118654752f));
            }
            if (WF32) {
                *(float2*)(Cf + (size_t)rA * N + col) = make_float2(v00, v01);
                *(float2*)(Cf + (size_t)rB * N + col) = make_float2(v10, v11);
            }
            if (WH) {
                *(__half2*)(Ch + (size_t)rA * N + col) =
                    __halves2half2(__float2half_rn(v00), __float2half_rn(v01));
                *(__half2*)(Ch + (size_t)rB * N + col) =
                    __halves2half2(__float2half_rn(v10), __float2half_rn(v11));
            }
        }
    }
}

// ======================= tensor-core flash attention (R11) =================
#define ASM_Q   0
#define KBUF(b) (16384 + (b) * 16384)
#define VBUF(b) (16384 + (b) * 16384 + 8192)
#define ATTN_SMEM 49152
#define NSCH (TT/64)   // 32
#define SCALE2 0.18033688011112042f   // 0.125 * log2(e)

__global__ void __launch_bounds__(256, 2) attn_mma(
    const __half* __restrict__ QKVp, __half* __restrict__ O)
{
    extern __shared__ char sm[];
    const uint32_t su = smem_u32(sm);

    const int tid  = threadIdx.x;
    const int wid  = tid >> 5;
    const int lane = tid & 31;
    const int q0 = blockIdx.x * 128;
    const int bh = blockIdx.y;
    const int b  = bh >> 4;
    const int h  = bh & 15;
    const size_t mrow0 = (size_t)b * TT;
    const size_t qbase = (mrow0 + q0) * QKV + h * HS;

    const int wm  = wid * 16;
    const int grp = lane >> 3, wi = lane & 7;

    #pragma unroll
    for (int i = 0; i < 4; i++) {
        int vec = tid + i * 256;
        int row = vec >> 3, ch = vec & 7;
        const size_t g = (qbase + (size_t)row * QKV + ch * 8) * 2;
        cp16(su + ASM_Q + sw8(row, ch), (const char*)QKVp + g);
    }
    CP_COMMIT();

    auto issueKV = [&](int s, int stg) {
        const size_t kb = ((mrow0 + (size_t)s * 64) * QKV + EE + h * HS) * 2;
        #pragma unroll
        for (int i = 0; i < 2; i++) {
            int vec = tid + i * 256;
            int row = vec >> 3, ch = vec & 7;
            const size_t off = ((size_t)row * QKV + ch * 8) * 2;
            cp16(su + KBUF(stg) + sw8(row, ch), (const char*)QKVp + kb + off);
            cp16(su + VBUF(stg) + sw8(row, ch), (const char*)QKVp + kb + EE*2 + off);
        }
    };
    issueKV(0, 0);
    CP_COMMIT();

    float m0 = -1e30f, m1 = -1e30f, l0 = 0.f, l1 = 0.f;
    float oacc[8][4];
    #pragma unroll
    for (int nt = 0; nt < 8; nt++)
        #pragma unroll
        for (int i = 0; i < 4; i++) oacc[nt][i] = 0.f;

    for (int s = 0; s < NSCH; s++) {
        const int stg = s & 1;
        CP_WAIT(0);
        __syncthreads();
        if (s + 1 < NSCH) {
            issueKV(s + 1, stg ^ 1);
            CP_COMMIT();
        }

        const uint32_t kbase = su + KBUF(stg);
        const uint32_t vbase = su + VBUF(stg);

        float sacc[8][4];
        #pragma unroll
        for (int nt = 0; nt < 8; nt++)
            #pragma unroll
            for (int i = 0; i < 4; i++) sacc[nt][i] = 0.f;

        #pragma unroll
        for (int ks = 0; ks < 4; ks++) {
            const int arow = wm + (lane & 15);
            const int achunk = ks * 2 + (lane >> 4);
            uint32_t qa[4];
            ldsm_x4(qa, su + ASM_Q + sw8(arow, achunk));

            uint32_t kf[8][2];
            #pragma unroll
            for (int bt = 0; bt < 4; bt++) {
                const int br = wi + ((grp >> 1) << 3) + bt * 16;
                const int bch = ks * 2 + (grp & 1);
                uint32_t r4[4];
                ldsm_x4(r4, kbase + sw8(br, bch));
                kf[bt*2][0] = r4[0]; kf[bt*2][1] = r4[1];
                kf[bt*2+1][0] = r4[2]; kf[bt*2+1][1] = r4[3];
            }
            #pragma unroll
            for (int nt = 0; nt < 8; nt++)
                mma16816(sacc[nt], qa[0], qa[1], qa[2], qa[3], kf[nt][0], kf[nt][1]);
        }

        float rmax0 = -1e30f, rmax1 = -1e30f;
        #pragma unroll
        for (int nt = 0; nt < 8; nt++) {
            #pragma unroll
            for (int i = 0; i < 4; i++) sacc[nt][i] *= SCALE2;
            rmax0 = fmaxf(rmax0, fmaxf(sacc[nt][0], sacc[nt][1]));
            rmax1 = fmaxf(rmax1, fmaxf(sacc[nt][2], sacc[nt][3]));
        }
        #pragma unroll
        for (int msk = 1; msk < 4; msk <<= 1) {
            rmax0 = fmaxf(rmax0, __shfl_xor_sync(0xffffffffu, rmax0, msk));
            rmax1 = fmaxf(rmax1, __shfl_xor_sync(0xffffffffu, rmax1, msk));
        }
        const float nm0 = fmaxf(m0, rmax0);
        const float nm1 = fmaxf(m1, rmax1);
        const float corr0 = ex2(m0 - nm0);
        const float corr1 = ex2(m1 - nm1);

        uint32_t pa[4][4];
        float sum0 = 0.f, sum1 = 0.f;
        #pragma unroll
        for (int nt = 0; nt < 8; nt++) {
            float p0 = ex2(sacc[nt][0] - nm0);
            float p1 = ex2(sacc[nt][1] - nm0);
            float p2 = ex2(sacc[nt][2] - nm1);
            float p3 = ex2(sacc[nt][3] - nm1);
            sum0 += p0 + p1;
            sum1 += p2 + p3;
            const int kt = nt >> 1, hf = nt & 1;
            pa[kt][hf*2]   = packh(__float2half_rn(p0), __float2half_rn(p1));
            pa[kt][hf*2+1] = packh(__float2half_rn(p2), __float2half_rn(p3));
        }
        #pragma unroll
        for (int msk = 1; msk < 4; msk <<= 1) {
            sum0 += __shfl_xor_sync(0xffffffffu, sum0, msk);
            sum1 += __shfl_xor_sync(0xffffffffu, sum1, msk);
        }
        l0 = l0 * corr0 + sum0;
        l1 = l1 * corr1 + sum1;
        m0 = nm0; m1 = nm1;
        #pragma unroll
        for (int nt = 0; nt < 8; nt++) {
            oacc[nt][0] *= corr0; oacc[nt][1] *= corr0;
            oacc[nt][2] *= corr1; oacc[nt][3] *= corr1;
        }

        #pragma unroll
        for (int ks = 0; ks < 4; ks++) {
            uint32_t vf[8][2];
            #pragma unroll
            for (int bt = 0; bt < 4; bt++) {
                const int key_row = ks * 16 + (grp & 1) * 8 + wi;
                const int dim_ch  = bt * 2 + (grp >> 1);
                uint32_t r4[4];
                ldsm_x4_t(r4, vbase + sw8(key_row, dim_ch));
                vf[bt*2][0] = r4[0]; vf[bt*2][1] = r4[1];
                vf[bt*2+1][0] = r4[2]; vf[bt*2+1][1] = r4[3];
            }
            #pragma unroll
            for (int nt = 0; nt < 8; nt++)
                mma16816(oacc[nt], pa[ks][0], pa[ks][1], pa[ks][2], pa[ks][3],
                         vf[nt][0], vf[nt][1]);
        }
    }

    const float inv0 = 1.0f / l0;
    const float inv1 = 1.0f / l1;
    const int r = lane >> 2;
    const int qcol = 2 * (lane & 3);
    const size_t row0 = (mrow0 + q0 + wm + r) * EE + h * HS;
    const size_t row1 = row0 + (size_t)8 * EE;
    #pragma unroll
    for (int nt = 0; nt < 8; nt++) {
        const int col = nt * 8 + qcol;
        *(__half2*)(O + row0 + col) = __halves2half2(
            __float2half_rn(oacc[nt][0] * inv0), __float2half_rn(oacc[nt][1] * inv0));
        *(__half2*)(O + row1 + col) = __halves2half2(
            __float2half_rn(oacc[nt][2] * inv1), __float2half_rn(oacc[nt][3] * inv1));
    }
}

// ======================= residual add + LayerNorm ==========================
// RF32=1: residual from fp32 (x); RF32=0: residual from fp16. fp16 out only.
template<int RF32>
__global__ __launch_bounds__(256) void add_ln(
    const float* __restrict__ af, const __half* __restrict__ ah,
    const __half* __restrict__ bsrc,
    const float* __restrict__ g, const float* __restrict__ beta,
    __half* __restrict__ oh)
{
    const int row = blockIdx.x;
    const int tid = threadIdx.x;
    float4 av;
    if (RF32) {
        av = ((const float4*)(af + (size_t)row * CC))[tid];
    } else {
        const __half2 a01 = ((const __half2*)(ah + (size_t)row * CC))[tid*2];
        const __half2 a23 = ((const __half2*)(ah + (size_t)row * CC))[tid*2 + 1];
        const float2 f01 = __half22float2(a01);
        const float2 f23 = __half22float2(a23);
        av = make_float4(f01.x, f01.y, f23.x, f23.y);
    }
    const __half2 h01 = ((const __half2*)(bsrc + (size_t)row * CC))[tid*2];
    const __half2 h23 = ((const __half2*)(bsrc + (size_t)row * CC))[tid*2 + 1];
    const float2 b01 = __half22float2(h01);
    const float2 b23 = __half22float2(h23);
    float4 v = make_float4(av.x + b01.x, av.y + b01.y, av.z + b23.x, av.w + b23.y);

    float s  = v.x + v.y + v.z + v.w;
    float ss = v.x*v.x + v.y*v.y + v.z*v.z + v.w*v.w;
    #pragma unroll
    for (int msk = 16; msk; msk >>= 1) {
        s  += __shfl_xor_sync(0xffffffffu, s,  msk);
        ss += __shfl_xor_sync(0xffffffffu, ss, msk);
    }
    __shared__ float ws[8], wss[8];
    __shared__ float mu_s, rstd_s;
    const int w = tid >> 5, lane = tid & 31;
    if (lane == 0) { ws[w] = s; wss[w] = ss; }
    __syncthreads();
    if (tid == 0) {
        float S = 0.f, SS = 0.f;
        #pragma unroll
        for (int i = 0; i < 8; i++) { S += ws[i]; SS += wss[i]; }
        float mu  = S * (1.0f / CC);
        float var = SS * (1.0f / CC) - mu * mu;
        mu_s   = mu;
        rstd_s = rsqrtf(var + 1e-5f);
    }
    __syncthreads();
    const float mu = mu_s, rstd = rstd_s;
    const float4 gv = ((const float4*)g)[tid];
    const float4 bv2 = ((const float4*)beta)[tid];
    float4 ov;
    ov.x = (v.x - mu) * rstd * gv.x + bv2.x;
    ov.y = (v.y - mu) * rstd * gv.y + bv2.y;
    ov.z = (v.z - mu) * rstd * gv.z + bv2.z;
    ov.w = (v.w - mu) * rstd * gv.w + bv2.w;

    size_t o = (size_t)row * CC + tid * 4;
    *(__half2*)(oh + o)     = __halves2half2(__float2half_rn(ov.x), __float2half_rn(ov.y));
    *(__half2*)(oh + o + 2) = __halves2half2(__float2half_rn(ov.z), __float2half_rn(ov.w));
}

// ======================= launch ============================================
extern "C" void kernel_launch(void* const* d_in, const int* in_sizes, int n_in,
                              void* d_out, int out_size)
{
    const float* x     = (const float*)d_in[0];
    const float* Wq    = (const float*)d_in[1];
    const float* bq    = (const float*)d_in[2];
    const float* Wk    = (const float*)d_in[3];
    const float* bk    = (const float*)d_in[4];
    const float* Wv    = (const float*)d_in[5];
    const float* bv    = (const float*)d_in[6];
    const float* Wo    = (const float*)d_in[7];
    const float* bo    = (const float*)d_in[8];
    const float* ln1_g = (const float*)d_in[9];
    const float* ln1_b = (const float*)d_in[10];
    const float* W1    = (const float*)d_in[11];
    const float* b1    = (const float*)d_in[12];
    const float* W2    = (const float*)d_in[13];
    const float* b2    = (const float*)d_in[14];
    const float* ln2_g = (const float*)d_in[15];
    const float* ln2_b = (const float*)d_in[16];
    const float* Wc    = (const float*)d_in[17];
    const float* bc    = (const float*)d_in[18];
    float* out = (float*)d_out;

    float *bqkv;
    cudaGetSymbolAddress((void**)&bqkv, g_bqkv);

    __half *tmph,*x16,*qkv,*a16,*o116,*f16,*o216,*wqkv,*wo,*w1,*w2,*wc;
    cudaGetSymbolAddress((void**)&tmph, g_tmph);
    cudaGetSymbolAddress((void**)&x16,  g_x16);
    cudaGetSymbolAddress((void**)&qkv,  g_qkv);
    cudaGetSymbolAddress((void**)&a16,  g_a16);
    cudaGetSymbolAddress((void**)&o116, g_o116);
    cudaGetSymbolAddress((void**)&f16,  g_f16);
    cudaGetSymbolAddress((void**)&o216, g_o216);
    cudaGetSymbolAddress((void**)&wqkv, g_wqkv);
    cudaGetSymbolAddress((void**)&wo,   g_wo);
    cudaGetSymbolAddress((void**)&w1,   g_w1);
    cudaGetSymbolAddress((void**)&w2,   g_w2);
    cudaGetSymbolAddress((void**)&wc,   g_wc);

    cudaFuncSetAttribute(gemm_mma<0,1,0>,
                         cudaFuncAttributeMaxDynamicSharedMemorySize, GEMM_SMEM);
    cudaFuncSetAttribute(gemm_mma<0,0,1>,
                         cudaFuncAttributeMaxDynamicSharedMemorySize, GEMM_SMEM);
    cudaFuncSetAttribute(gemm_mma<1,0,1>,
                         cudaFuncAttributeMaxDynamicSharedMemorySize, GEMM_SMEM);
    cudaFuncSetAttribute(attn_mma,
                         cudaFuncAttributeMaxDynamicSharedMemorySize, ATTN_SMEM);

    // --- all prep in ONE launch ---
    prep_all<<<PREP_GRID, 256>>>(Wq, Wk, Wv, Wo, W1, W2, Wc, x, bq, bk, bv,
                                 wqkv, wo, w1, w2, wc, x16, bqkv);

    // --- fused QKV projection (N = 3072) ---
    const dim3 gQKV(QKV/128, MM/128);
    const dim3 gC(CC/128, MM/128);
    const dim3 gF(FF/128, MM/128);
    gemm_mma<0,0,1><<<gQKV, 256, GEMM_SMEM>>>(x16, wqkv, bqkv, nullptr, qkv, MM, QKV, CC);

    // --- attention ---
    attn_mma<<<dim3(TT/128, BB*HH), 256, ATTN_SMEM>>>(qkv, a16);

    // --- output projection (fp16 out) + residual + LN1 ---
    gemm_mma<0,0,1><<<gC, 256, GEMM_SMEM>>>(a16, wo, bo, nullptr, tmph, MM, CC, EE);
    add_ln<1><<<MM, 256>>>(x, nullptr, tmph, ln1_g, ln1_b, o116);

    // --- FFN ---
    gemm_mma<1,0,1><<<gF, 256, GEMM_SMEM>>>(o116, w1, b1, nullptr, f16, MM, FF, CC);
    gemm_mma<0,0,1><<<gC, 256, GEMM_SMEM>>>(f16, w2, b2, nullptr, tmph, MM, CC, FF);
    add_ln<0><<<MM, 256>>>(nullptr, o116, tmph, ln2_g, ln2_b, o216);

    // --- final pointwise conv: out = out2 @ Wc^T + bc ---
    gemm_mma<0,1,0><<<gC, 256, GEMM_SMEM>>>(o216, wc, bc, out, nullptr, MM, CC, CC);
}

// round 16
// speedup vs baseline: 1.2101x; 1.0079x over previous
#include <cuda_runtime.h>
#include <cuda_fp16.h>
#include <math.h>
#include <stdint.h>

// Problem dims (fixed)
#define BB   2
#define TT   2048
#define CC   1024
#define EE   1024
#define HH   16
#define HS   64
#define FF   4096
#define MM   (BB*TT)   // 4096 rows
#define QKV  (3*EE)    // 3072

// ======================= scratch (static device globals) ===================
__device__ float g_bqkv[QKV];

__device__ __half g_tmph[MM*CC];      // fp16 GEMM outputs feeding add_ln
__device__ __half g_x16 [MM*CC];
__device__ __half g_qkv [MM*QKV];
__device__ __half g_a16 [MM*EE];
__device__ __half g_o116[MM*CC];
__device__ __half g_f16 [MM*FF];
__device__ __half g_o216[MM*CC];
// transposed weights: [N, K] fp16
__device__ __half g_wqkv[QKV*CC];
__device__ __half g_wo  [CC*EE];
__device__ __half g_w1  [FF*CC];
__device__ __half g_w2  [CC*FF];
__device__ __half g_wc  [CC*CC];

// ======================= small PTX helpers =================================
__device__ __forceinline__ uint32_t smem_u32(const void* p) {
    uint32_t a;
    asm("{ .reg .u64 t; cvta.to.shared.u64 t, %1; cvt.u32.u64 %0, t; }"
        : "=r"(a) : "l"(p));
    return a;
}
__device__ __forceinline__ void cp16(uint32_t saddr, const void* gaddr) {
    asm volatile("cp.async.cg.shared.global [%0], [%1], 16;"
                 :: "r"(saddr), "l"(gaddr) : "memory");
}
#define CP_COMMIT() asm volatile("cp.async.commit_group;" ::: "memory")
#define CP_WAIT(n)  asm volatile("cp.async.wait_group %0;" :: "n"(n) : "memory")

__device__ __forceinline__ void ldsm_x4(uint32_t r[4], uint32_t addr) {
    asm volatile("ldmatrix.sync.aligned.m8n8.x4.shared.b16 {%0,%1,%2,%3}, [%4];"
                 : "=r"(r[0]), "=r"(r[1]), "=r"(r[2]), "=r"(r[3]) : "r"(addr));
}
__device__ __forceinline__ void ldsm_x4_t(uint32_t r[4], uint32_t addr) {
    asm volatile("ldmatrix.sync.aligned.m8n8.x4.trans.shared.b16 {%0,%1,%2,%3}, [%4];"
                 : "=r"(r[0]), "=r"(r[1]), "=r"(r[2]), "=r"(r[3]) : "r"(addr));
}
__device__ __forceinline__ void mma16816(float c[4],
    uint32_t a0, uint32_t a1, uint32_t a2, uint32_t a3, uint32_t b0, uint32_t b1)
{
    asm volatile(
        "mma.sync.aligned.m16n8k16.row.col.f32.f16.f16.f32 "
        "{%0,%1,%2,%3}, {%4,%5,%6,%7}, {%8,%9}, {%0,%1,%2,%3};"
        : "+f"(c[0]), "+f"(c[1]), "+f"(c[2]), "+f"(c[3])
        : "r"(a0), "r"(a1), "r"(a2), "r"(a3), "r"(b0), "r"(b1));
}
__device__ __forceinline__ uint32_t packh(__half a, __half b) {
    __half2 t = __halves2half2(a, b);
    return *(uint32_t*)&t;
}
__device__ __forceinline__ float ex2(float x) {
    float y;
    asm("ex2.approx.f32 %0, %1;" : "=f"(y) : "f"(x));
    return y;
}

// ======================= fused prep kernel =================================
__device__ __forceinline__ void transpose_block(
    const float* __restrict__ W, __half* __restrict__ T,
    int K, int N, int bb, float (*t)[33])
{
    const int nb = N >> 5;
    const int bx = bb % nb, by = bb / nb;
    const int n0 = bx * 32, k0 = by * 32;
    const int tx = threadIdx.x & 31, ty = threadIdx.x >> 5;
    #pragma unroll
    for (int s = 0; s < 32; s += 8)
        t[ty + s][tx] = W[(size_t)(k0 + ty + s) * N + n0 + tx];
    __syncthreads();
    #pragma unroll
    for (int s = 0; s < 32; s += 8)
        T[(size_t)(n0 + ty + s) * K + k0 + tx] = __float2half_rn(t[tx][ty + s]);
}
__device__ __forceinline__ void convert_block(
    const float* __restrict__ in, __half* __restrict__ o, int bb)
{
    const int idx = bb * 1024 + threadIdx.x * 4;
    float4 v = *(const float4*)(in + idx);
    *(__half2*)(o + idx)     = __halves2half2(__float2half_rn(v.x), __float2half_rn(v.y));
    *(__half2*)(o + idx + 2) = __halves2half2(__float2half_rn(v.z), __float2half_rn(v.w));
}

#define PREP_GRID 17411

__global__ __launch_bounds__(256) void prep_all(
    const float* __restrict__ Wq, const float* __restrict__ Wk,
    const float* __restrict__ Wv, const float* __restrict__ Wo,
    const float* __restrict__ W1, const float* __restrict__ W2,
    const float* __restrict__ Wc, const float* __restrict__ x,
    const float* __restrict__ bq, const float* __restrict__ bk,
    const float* __restrict__ bv,
    __half* __restrict__ wqkv, __half* __restrict__ wo,
    __half* __restrict__ w1,   __half* __restrict__ w2,
    __half* __restrict__ wc,   __half* __restrict__ x16,
    float* __restrict__ bqkv)
{
    __shared__ float t[32][33];
    const int b = blockIdx.x;
    if (b < 3072) {
        const int seg = b >> 10, bb = b & 1023;
        const float* W = (seg == 0) ? Wq : (seg == 1) ? Wk : Wv;
        transpose_block(W, wqkv + (size_t)seg * EE * CC, CC, EE, bb, t);
    } else if (b < 4096) {
        transpose_block(Wo, wo, EE, CC, b - 3072, t);
    } else if (b < 8192) {
        transpose_block(W1, w1, CC, FF, b - 4096, t);
    } else if (b < 12288) {
        transpose_block(W2, w2, FF, CC, b - 8192, t);
    } else if (b < 13312) {
        convert_block(Wc, wc, b - 12288);
    } else if (b < 17408) {
        convert_block(x, x16, b - 13312);
    } else {
        const int bb = b - 17408;
        const float* src = (bb == 0) ? bq : (bb == 1) ? bk : bv;
        ((float4*)(bqkv + bb * EE))[threadIdx.x] = ((const float4*)src)[threadIdx.x];
    }
}

// ======================= swizzle (128B rows, 8 x 16B chunks) ===============
__device__ __forceinline__ uint32_t sw8(int row, int ch) {
    return (uint32_t)(row * 128 + ((ch ^ (row & 7)) << 4));
}

// ======================= HMMA fp16 GEMM (R11: BK=64, 2-stage, 1 sync) ======
#define STAGE_BYTES 32768
#define ARR_A 0
#define ARR_B 16384
#define GEMM_SMEM (2*STAGE_BYTES)

template<int GELU, int WF32, int WH>
__global__ __launch_bounds__(256, 2) void gemm_mma(
    const __half* __restrict__ A, const __half* __restrict__ Bw,
    const float* __restrict__ bias,
    float* __restrict__ Cf, __half* __restrict__ Ch,
    int M, int N, int K)
{
    extern __shared__ char sm[];
    const uint32_t su = smem_u32(sm);

    const int tid  = threadIdx.x;
    const int wid  = tid >> 5;
    const int lane = tid & 31;
    const int m0 = blockIdx.y * 128;
    const int n0 = blockIdx.x * 128;
    const int wm0 = (wid & 1) * 64;
    const int wn0 = (wid >> 1) * 32;

    float acc[4][4][4];
    #pragma unroll
    for (int mt = 0; mt < 4; mt++)
        #pragma unroll
        for (int nt = 0; nt < 4; nt++)
            #pragma unroll
            for (int i = 0; i < 4; i++) acc[mt][nt][i] = 0.f;

    const int nCh = K >> 6;   // 64-wide chunks

    auto issue = [&](int c, int stg) {
        const uint32_t sbase = su + stg * STAGE_BYTES;
        #pragma unroll
        for (int i = 0; i < 4; i++) {
            const int vec = tid + i * 256;
            const int row = vec >> 3;
            const int ch  = vec & 7;
            const uint32_t so = sw8(row, ch);
            const size_t gA = ((size_t)(m0 + row) * K + c * 64 + ch * 8) * 2;
            const size_t gB = ((size_t)(n0 + row) * K + c * 64 + ch * 8) * 2;
            cp16(sbase + ARR_A + so, (const char*)A  + gA);
            cp16(sbase + ARR_B + so, (const char*)Bw + gB);
        }
    };

    issue(0, 0);
    CP_COMMIT();

    const int grp = lane >> 3, wi = lane & 7;

    for (int c = 0; c < nCh; c++) {
        const int stg = c & 1;
        CP_WAIT(0);
        __syncthreads();
        if (c + 1 < nCh) {
            issue(c + 1, stg ^ 1);
            CP_COMMIT();
        }

        const uint32_t sbase = su + stg * STAGE_BYTES;

        #pragma unroll
        for (int ks = 0; ks < 4; ks++) {
            uint32_t bfr[4][2];
            const int brow_base = wn0 + wi + ((grp >> 1) << 3);
            const int bchunk = ks * 2 + (grp & 1);
            #pragma unroll
            for (int bt = 0; bt < 2; bt++) {
                uint32_t r4[4];
                const int br = brow_base + bt * 16;
                ldsm_x4(r4, sbase + ARR_B + sw8(br, bchunk));
                bfr[bt*2][0]   = r4[0]; bfr[bt*2][1]   = r4[1];
                bfr[bt*2+1][0] = r4[2]; bfr[bt*2+1][1] = r4[3];
            }

            const int arow = wm0 + (lane & 15);
            const int achunk = ks * 2 + (lane >> 4);
            uint32_t a[4][4];
            #pragma unroll
            for (int mt = 0; mt < 4; mt++)
                ldsm_x4(a[mt], sbase + ARR_A + sw8(arow + mt * 16, achunk));
            #pragma unroll
            for (int mt = 0; mt < 4; mt++)
                #pragma unroll
                for (int nt = 0; nt < 4; nt++)
                    mma16816(acc[mt][nt], a[mt][0], a[mt][1], a[mt][2], a[mt][3],
                             bfr[nt][0], bfr[nt][1]);
        }
    }

    const int er = lane >> 2;
    const int ec = (lane & 3) * 2;
    #pragma unroll
    for (int mt = 0; mt < 4; mt++) {
        #pragma unroll
        for (int nt = 0; nt < 4; nt++) {
            const int col = n0 + wn0 + nt * 8 + ec;
            const float b0 = bias[col], b1 = bias[col + 1];
            const int rA = m0 + wm0 + mt * 16 + er;
            const int rB = rA + 8;
            float v00 = acc[mt][nt][0] + b0;
            float v01 = acc[mt][nt][1] + b1;
            float v10 = acc[mt][nt][2] + b0;
            float v11 = acc[mt][nt][3] + b1;
            if (GELU) {
                v00 = 0.5f * v00 * (1.0f + erff(v00 * 0.70710678118654752f));
                v01 = 0.5f * v01 * (1.0f + erff(v01 * 0.70710678118654752f));
                v10 = 0.5f * v10 * (1.0f + erff(v10 * 0.70710678118654752f));
                v11 = 0.5f * v11 * (1.0f + erff(v11 * 0.70710678118654752f));
            }
            if (WF32) {
                *(float2*)(Cf + (size_t)rA * N + col) = make_float2(v00, v01);
                *(float2*)(Cf + (size_t)rB * N + col) = make_float2(v10, v11);
            }
            if (WH) {
                *(__half2*)(Ch + (size_t)rA * N + col) =
                    __halves2half2(__float2half_rn(v00), __float2half_rn(v01));
                *(__half2*)(Ch + (size_t)rB * N + col) =
                    __halves2half2(__float2half_rn(v10), __float2half_rn(v11));
            }
        }
    }
}

// ======================= tensor-core flash attention ========================
// R15 + hoisted Q fragments (Q is chunk-invariant; load its 16 regs once).
#define ASM_Q   0
#define KBUF(b) (16384 + (b) * 16384)
#define VBUF(b) (16384 + (b) * 16384 + 8192)
#define ATTN_SMEM 49152
#define NSCH (TT/64)   // 32
#define SCALE2 0.18033688011112042f   // 0.125 * log2(e)

__global__ void __launch_bounds__(256, 2) attn_mma(
    const __half* __restrict__ QKVp, __half* __restrict__ O)
{
    extern __shared__ char sm[];
    const uint32_t su = smem_u32(sm);

    const int tid  = threadIdx.x;
    const int wid  = tid >> 5;
    const int lane = tid & 31;
    const int q0 = blockIdx.x * 128;
    const int bh = blockIdx.y;
    const int b  = bh >> 4;
    const int h  = bh & 15;
    const size_t mrow0 = (size_t)b * TT;
    const size_t qbase = (mrow0 + q0) * QKV + h * HS;

    const int wm  = wid * 16;
    const int grp = lane >> 3, wi = lane & 7;

    // Q tile load (group 0)
    #pragma unroll
    for (int i = 0; i < 4; i++) {
        int vec = tid + i * 256;
        int row = vec >> 3, ch = vec & 7;
        const size_t g = (qbase + (size_t)row * QKV + ch * 8) * 2;
        cp16(su + ASM_Q + sw8(row, ch), (const char*)QKVp + g);
    }
    CP_COMMIT();

    auto issueKV = [&](int s, int stg) {
        const size_t kb = ((mrow0 + (size_t)s * 64) * QKV + EE + h * HS) * 2;
        #pragma unroll
        for (int i = 0; i < 2; i++) {
            int vec = tid + i * 256;
            int row = vec >> 3, ch = vec & 7;
            const size_t off = ((size_t)row * QKV + ch * 8) * 2;
            cp16(su + KBUF(stg) + sw8(row, ch), (const char*)QKVp + kb + off);
            cp16(su + VBUF(stg) + sw8(row, ch), (const char*)QKVp + kb + EE*2 + off);
        }
    };
    issueKV(0, 0);
    CP_COMMIT();

    CP_WAIT(0);          // Q + KV(0) landed
    __syncthreads();

    // ---- hoist Q fragments (invariant across all KV chunks) ----
    uint32_t qa[4][4];
    {
        const int arow = wm + (lane & 15);
        #pragma unroll
        for (int ks = 0; ks < 4; ks++) {
            const int achunk = ks * 2 + (lane >> 4);
            ldsm_x4(qa[ks], su + ASM_Q + sw8(arow, achunk));
        }
    }

    float m0 = -1e30f, m1 = -1e30f, l0 = 0.f, l1 = 0.f;
    float oacc[8][4];
    #pragma unroll
    for (int nt = 0; nt < 8; nt++)
        #pragma unroll
        for (int i = 0; i < 4; i++) oacc[nt][i] = 0.f;

    for (int s = 0; s < NSCH; s++) {
        const int stg = s & 1;
        if (s > 0) {
            CP_WAIT(0);
            __syncthreads();   // KV(s) landed; compute(s-1) done in all warps
        }
        if (s + 1 < NSCH) {
            issueKV(s + 1, stg ^ 1);
            CP_COMMIT();
        }

        const uint32_t kbase = su + KBUF(stg);
        const uint32_t vbase = su + VBUF(stg);

        // ---- S = Q K^T ----
        float sacc[8][4];
        #pragma unroll
        for (int nt = 0; nt < 8; nt++)
            #pragma unroll
            for (int i = 0; i < 4; i++) sacc[nt][i] = 0.f;

        #pragma unroll
        for (int ks = 0; ks < 4; ks++) {
            uint32_t kf[8][2];
            #pragma unroll
            for (int bt = 0; bt < 4; bt++) {
                const int br = wi + ((grp >> 1) << 3) + bt * 16;
                const int bch = ks * 2 + (grp & 1);
                uint32_t r4[4];
                ldsm_x4(r4, kbase + sw8(br, bch));
                kf[bt*2][0] = r4[0]; kf[bt*2][1] = r4[1];
                kf[bt*2+1][0] = r4[2]; kf[bt*2+1][1] = r4[3];
            }
            #pragma unroll
            for (int nt = 0; nt < 8; nt++)
                mma16816(sacc[nt], qa[ks][0], qa[ks][1], qa[ks][2], qa[ks][3],
                         kf[nt][0], kf[nt][1]);
        }

        // ---- online softmax (exp2 domain) ----
        float rmax0 = -1e30f, rmax1 = -1e30f;
        #pragma unroll
        for (int nt = 0; nt < 8; nt++) {
            #pragma unroll
            for (int i = 0; i < 4; i++) sacc[nt][i] *= SCALE2;
            rmax0 = fmaxf(rmax0, fmaxf(sacc[nt][0], sacc[nt][1]));
            rmax1 = fmaxf(rmax1, fmaxf(sacc[nt][2], sacc[nt][3]));
        }
        #pragma unroll
        for (int msk = 1; msk < 4; msk <<= 1) {
            rmax0 = fmaxf(rmax0, __shfl_xor_sync(0xffffffffu, rmax0, msk));
            rmax1 = fmaxf(rmax1, __shfl_xor_sync(0xffffffffu, rmax1, msk));
        }
        const float nm0 = fmaxf(m0, rmax0);
        const float nm1 = fmaxf(m1, rmax1);
        const float corr0 = ex2(m0 - nm0);
        const float corr1 = ex2(m1 - nm1);

        uint32_t pa[4][4];
        float sum0 = 0.f, sum1 = 0.f;
        #pragma unroll
        for (int nt = 0; nt < 8; nt++) {
            float p0 = ex2(sacc[nt][0] - nm0);
            float p1 = ex2(sacc[nt][1] - nm0);
            float p2 = ex2(sacc[nt][2] - nm1);
            float p3 = ex2(sacc[nt][3] - nm1);
            sum0 += p0 + p1;
            sum1 += p2 + p3;
            const int kt = nt >> 1, hf = nt & 1;
            pa[kt][hf*2]   = packh(__float2half_rn(p0), __float2half_rn(p1));
            pa[kt][hf*2+1] = packh(__float2half_rn(p2), __float2half_rn(p3));
        }
        #pragma unroll
        for (int msk = 1; msk < 4; msk <<= 1) {
            sum0 += __shfl_xor_sync(0xffffffffu, sum0, msk);
            sum1 += __shfl_xor_sync(0xffffffffu, sum1, msk);
        }
        l0 = l0 * corr0 + sum0;
        l1 = l1 * corr1 + sum1;
        m0 = nm0; m1 = nm1;
        #pragma unroll
        for (int nt = 0; nt < 8; nt++) {
            oacc[nt][0] *= corr0; oacc[nt][1] *= corr0;
            oacc[nt][2] *= corr1; oacc[nt][3] *= corr1;
        }

        // ---- O += P V ----
        #pragma unroll
        for (int ks = 0; ks < 4; ks++) {
            uint32_t vf[8][2];
            #pragma unroll
            for (int bt = 0; bt < 4; bt++) {
                const int key_row = ks * 16 + (grp & 1) * 8 + wi;
                const int dim_ch  = bt * 2 + (grp >> 1);
                uint32_t r4[4];
                ldsm_x4_t(r4, vbase + sw8(key_row, dim_ch));
                vf[bt*2][0] = r4[0]; vf[bt*2][1] = r4[1];
                vf[bt*2+1][0] = r4[2]; vf[bt*2+1][1] = r4[3];
            }
            #pragma unroll
            for (int nt = 0; nt < 8; nt++)
                mma16816(oacc[nt], pa[ks][0], pa[ks][1], pa[ks][2], pa[ks][3],
                         vf[nt][0], vf[nt][1]);
        }
    }

    const float inv0 = 1.0f / l0;
    const float inv1 = 1.0f / l1;
    const int r = lane >> 2;
    const int qcol = 2 * (lane & 3);
    const size_t row0 = (mrow0 + q0 + wm + r) * EE + h * HS;
    const size_t row1 = row0 + (size_t)8 * EE;
    #pragma unroll
    for (int nt = 0; nt < 8; nt++) {
        const int col = nt * 8 + qcol;
        *(__half2*)(O + row0 + col) = __halves2half2(
            __float2half_rn(oacc[nt][0] * inv0), __float2half_rn(oacc[nt][1] * inv0));
        *(__half2*)(O + row1 + col) = __halves2half2(
            __float2half_rn(oacc[nt][2] * inv1), __float2half_rn(oacc[nt][3] * inv1));
    }
}

// ======================= residual add + LayerNorm ==========================
// RF32=1: residual from fp32 (x); RF32=0: residual from fp16. fp16 out only.
template<int RF32>
__global__ __launch_bounds__(256) void add_ln(
    const float* __restrict__ af, const __half* __restrict__ ah,
    const __half* __restrict__ bsrc,
    const float* __restrict__ g, const float* __restrict__ beta,
    __half* __restrict__ oh)
{
    const int row = blockIdx.x;
    const int tid = threadIdx.x;
    float4 av;
    if (RF32) {
        av = ((const float4*)(af + (size_t)row * CC))[tid];
    } else {
        const __half2 a01 = ((const __half2*)(ah + (size_t)row * CC))[tid*2];
        const __half2 a23 = ((const __half2*)(ah + (size_t)row * CC))[tid*2 + 1];
        const float2 f01 = __half22float2(a01);
        const float2 f23 = __half22float2(a23);
        av = make_float4(f01.x, f01.y, f23.x, f23.y);
    }
    const __half2 h01 = ((const __half2*)(bsrc + (size_t)row * CC))[tid*2];
    const __half2 h23 = ((const __half2*)(bsrc + (size_t)row * CC))[tid*2 + 1];
    const float2 b01 = __half22float2(h01);
    const float2 b23 = __half22float2(h23);
    float4 v = make_float4(av.x + b01.x, av.y + b01.y, av.z + b23.x, av.w + b23.y);

    float s  = v.x + v.y + v.z + v.w;
    float ss = v.x*v.x + v.y*v.y + v.z*v.z + v.w*v.w;
    #pragma unroll
    for (int msk = 16; msk; msk >>= 1) {
        s  += __shfl_xor_sync(0xffffffffu, s,  msk);
        ss += __shfl_xor_sync(0xffffffffu, ss, msk);
    }
    __shared__ float ws[8], wss[8];
    __shared__ float mu_s, rstd_s;
    const int w = tid >> 5, lane = tid & 31;
    if (lane == 0) { ws[w] = s; wss[w] = ss; }
    __syncthreads();
    if (tid == 0) {
        float S = 0.f, SS = 0.f;
        #pragma unroll
        for (int i = 0; i < 8; i++) { S += ws[i]; SS += wss[i]; }
        float mu  = S * (1.0f / CC);
        float var = SS * (1.0f / CC) - mu * mu;
        mu_s   = mu;
        rstd_s = rsqrtf(var + 1e-5f);
    }
    __syncthreads();
    const float mu = mu_s, rstd = rstd_s;
    const float4 gv = ((const float4*)g)[tid];
    const float4 bv2 = ((const float4*)beta)[tid];
    float4 ov;
    ov.x = (v.x - mu) * rstd * gv.x + bv2.x;
    ov.y = (v.y - mu) * rstd * gv.y + bv2.y;
    ov.z = (v.z - mu) * rstd * gv.z + bv2.z;
    ov.w = (v.w - mu) * rstd * gv.w + bv2.w;

    size_t o = (size_t)row * CC + tid * 4;
    *(__half2*)(oh + o)     = __halves2half2(__float2half_rn(ov.x), __float2half_rn(ov.y));
    *(__half2*)(oh + o + 2) = __halves2half2(__float2half_rn(ov.z), __float2half_rn(ov.w));
}

// ======================= launch ============================================
extern "C" void kernel_launch(void* const* d_in, const int* in_sizes, int n_in,
                              void* d_out, int out_size)
{
    const float* x     = (const float*)d_in[0];
    const float* Wq    = (const float*)d_in[1];
    const float* bq    = (const float*)d_in[2];
    const float* Wk    = (const float*)d_in[3];
    const float* bk    = (const float*)d_in[4];
    const float* Wv    = (const float*)d_in[5];
    const float* bv    = (const float*)d_in[6];
    const float* Wo    = (const float*)d_in[7];
    const float* bo    = (const float*)d_in[8];
    const float* ln1_g = (const float*)d_in[9];
    const float* ln1_b = (const float*)d_in[10];
    const float* W1    = (const float*)d_in[11];
    const float* b1    = (const float*)d_in[12];
    const float* W2    = (const float*)d_in[13];
    const float* b2    = (const float*)d_in[14];
    const float* ln2_g = (const float*)d_in[15];
    const float* ln2_b = (const float*)d_in[16];
    const float* Wc    = (const float*)d_in[17];
    const float* bc    = (const float*)d_in[18];
    float* out = (float*)d_out;

    float *bqkv;
    cudaGetSymbolAddress((void**)&bqkv, g_bqkv);

    __half *tmph,*x16,*qkv,*a16,*o116,*f16,*o216,*wqkv,*wo,*w1,*w2,*wc;
    cudaGetSymbolAddress((void**)&tmph, g_tmph);
    cudaGetSymbolAddress((void**)&x16,  g_x16);
    cudaGetSymbolAddress((void**)&qkv,  g_qkv);
    cudaGetSymbolAddress((void**)&a16,  g_a16);
    cudaGetSymbolAddress((void**)&o116, g_o116);
    cudaGetSymbolAddress((void**)&f16,  g_f16);
    cudaGetSymbolAddress((void**)&o216, g_o216);
    cudaGetSymbolAddress((void**)&wqkv, g_wqkv);
    cudaGetSymbolAddress((void**)&wo,   g_wo);
    cudaGetSymbolAddress((void**)&w1,   g_w1);
    cudaGetSymbolAddress((void**)&w2,   g_w2);
    cudaGetSymbolAddress((void**)&wc,   g_wc);

    cudaFuncSetAttribute(gemm_mma<0,1,0>,
                         cudaFuncAttributeMaxDynamicSharedMemorySize, GEMM_SMEM);
    cudaFuncSetAttribute(gemm_mma<0,0,1>,
                         cudaFuncAttributeMaxDynamicSharedMemorySize, GEMM_SMEM);
    cudaFuncSetAttribute(gemm_mma<1,0,1>,
                         cudaFuncAttributeMaxDynamicSharedMemorySize, GEMM_SMEM);
    cudaFuncSetAttribute(attn_mma,
                         cudaFuncAttributeMaxDynamicSharedMemorySize, ATTN_SMEM);

    // --- all prep in ONE launch ---
    prep_all<<<PREP_GRID, 256>>>(Wq, Wk, Wv, Wo, W1, W2, Wc, x, bq, bk, bv,
                                 wqkv, wo, w1, w2, wc, x16, bqkv);

    // --- fused QKV projection (N = 3072) ---
    const dim3 gQKV(QKV/128, MM/128);
    const dim3 gC(CC/128, MM/128);
    const dim3 gF(FF/128, MM/128);
    gemm_mma<0,0,1><<<gQKV, 256, GEMM_SMEM>>>(x16, wqkv, bqkv, nullptr, qkv, MM, QKV, CC);

    // --- attention ---
    attn_mma<<<dim3(TT/128, BB*HH), 256, ATTN_SMEM>>>(qkv, a16);

    // --- output projection (fp16 out) + residual + LN1 ---
    gemm_mma<0,0,1><<<gC, 256, GEMM_SMEM>>>(a16, wo, bo, nullptr, tmph, MM, CC, EE);
    add_ln<1><<<MM, 256>>>(x, nullptr, tmph, ln1_g, ln1_b, o116);

    // --- FFN ---
    gemm_mma<1,0,1><<<gF, 256, GEMM_SMEM>>>(o116, w1, b1, nullptr, f16, MM, FF, CC);
    gemm_mma<0,0,1><<<gC, 256, GEMM_SMEM>>>(f16, w2, b2, nullptr, tmph, MM, CC, FF);
    add_ln<0><<<MM, 256>>>(nullptr, o116, tmph, ln2_g, ln2_b, o216);

    // --- final pointwise conv: out = out2 @ Wc^T + bc ---
    gemm_mma<0,1,0><<<gC, 256, GEMM_SMEM>>>(o216, wc, bc, out, nullptr, MM, CC, CC);
}

// round 17
// speedup vs baseline: 1.2102x; 1.0001x over previous
#include <cuda_runtime.h>
#include <cuda_fp16.h>
#include <math.h>
#include <stdint.h>

// Problem dims (fixed)
#define BB   2
#define TT   2048
#define CC   1024
#define EE   1024
#define HH   16
#define HS   64
#define FF   4096
#define MM   (BB*TT)   // 4096 rows
#define QKV  (3*EE)    // 3072

// ======================= scratch (static device globals) ===================
__device__ float g_bqkv[QKV];

__device__ __half g_tmph[MM*CC];
__device__ __half g_x16 [MM*CC];
__device__ __half g_qkv [MM*QKV];
__device__ __half g_a16 [MM*EE];
__device__ __half g_o116[MM*CC];
__device__ __half g_f16 [MM*FF];
__device__ __half g_o216[MM*CC];
// transposed weights: [N, K] fp16
__device__ __half g_wqkv[QKV*CC];
__device__ __half g_wo  [CC*EE];
__device__ __half g_w1  [FF*CC];
__device__ __half g_w2  [CC*FF];
__device__ __half g_wc  [CC*CC];

// ======================= small PTX helpers =================================
__device__ __forceinline__ uint32_t smem_u32(const void* p) {
    uint32_t a;
    asm("{ .reg .u64 t; cvta.to.shared.u64 t, %1; cvt.u32.u64 %0, t; }"
        : "=r"(a) : "l"(p));
    return a;
}
__device__ __forceinline__ void cp16(uint32_t saddr, const void* gaddr) {
    asm volatile("cp.async.cg.shared.global [%0], [%1], 16;"
                 :: "r"(saddr), "l"(gaddr) : "memory");
}
#define CP_COMMIT() asm volatile("cp.async.commit_group;" ::: "memory")
#define CP_WAIT(n)  asm volatile("cp.async.wait_group %0;" :: "n"(n) : "memory")

__device__ __forceinline__ void ldsm_x4(uint32_t r[4], uint32_t addr) {
    asm volatile("ldmatrix.sync.aligned.m8n8.x4.shared.b16 {%0,%1,%2,%3}, [%4];"
                 : "=r"(r[0]), "=r"(r[1]), "=r"(r[2]), "=r"(r[3]) : "r"(addr));
}
__device__ __forceinline__ void ldsm_x4_t(uint32_t r[4], uint32_t addr) {
    asm volatile("ldmatrix.sync.aligned.m8n8.x4.trans.shared.b16 {%0,%1,%2,%3}, [%4];"
                 : "=r"(r[0]), "=r"(r[1]), "=r"(r[2]), "=r"(r[3]) : "r"(addr));
}
__device__ __forceinline__ void mma16816(float c[4],
    uint32_t a0, uint32_t a1, uint32_t a2, uint32_t a3, uint32_t b0, uint32_t b1)
{
    asm volatile(
        "mma.sync.aligned.m16n8k16.row.col.f32.f16.f16.f32 "
        "{%0,%1,%2,%3}, {%4,%5,%6,%7}, {%8,%9}, {%0,%1,%2,%3};"
        : "+f"(c[0]), "+f"(c[1]), "+f"(c[2]), "+f"(c[3])
        : "r"(a0), "r"(a1), "r"(a2), "r"(a3), "r"(b0), "r"(b1));
}
__device__ __forceinline__ uint32_t packh(__half a, __half b) {
    __half2 t = __halves2half2(a, b);
    return *(uint32_t*)&t;
}
__device__ __forceinline__ float ex2(float x) {
    float y;
    asm("ex2.approx.f32 %0, %1;" : "=f"(y) : "f"(x));
    return y;
}

// ======================= fused prep kernel =================================
__device__ __forceinline__ void transpose_block(
    const float* __restrict__ W, __half* __restrict__ T,
    int K, int N, int bb, float (*t)[33])
{
    const int nb = N >> 5;
    const int bx = bb % nb, by = bb / nb;
    const int n0 = bx * 32, k0 = by * 32;
    const int tx = threadIdx.x & 31, ty = threadIdx.x >> 5;
    #pragma unroll
    for (int s = 0; s < 32; s += 8)
        t[ty + s][tx] = W[(size_t)(k0 + ty + s) * N + n0 + tx];
    __syncthreads();
    #pragma unroll
    for (int s = 0; s < 32; s += 8)
        T[(size_t)(n0 + ty + s) * K + k0 + tx] = __float2half_rn(t[tx][ty + s]);
}
__device__ __forceinline__ void convert_block(
    const float* __restrict__ in, __half* __restrict__ o, int bb)
{
    const int idx = bb * 1024 + threadIdx.x * 4;
    float4 v = *(const float4*)(in + idx);
    *(__half2*)(o + idx)     = __halves2half2(__float2half_rn(v.x), __float2half_rn(v.y));
    *(__half2*)(o + idx + 2) = __halves2half2(__float2half_rn(v.z), __float2half_rn(v.w));
}

#define PREP_GRID 17411

__global__ __launch_bounds__(256) void prep_all(
    const float* __restrict__ Wq, const float* __restrict__ Wk,
    const float* __restrict__ Wv, const float* __restrict__ Wo,
    const float* __restrict__ W1, const float* __restrict__ W2,
    const float* __restrict__ Wc, const float* __restrict__ x,
    const float* __restrict__ bq, const float* __restrict__ bk,
    const float* __restrict__ bv,
    __half* __restrict__ wqkv, __half* __restrict__ wo,
    __half* __restrict__ w1,   __half* __restrict__ w2,
    __half* __restrict__ wc,   __half* __restrict__ x16,
    float* __restrict__ bqkv)
{
    __shared__ float t[32][33];
    const int b = blockIdx.x;
    if (b < 3072) {
        const int seg = b >> 10, bb = b & 1023;
        const float* W = (seg == 0) ? Wq : (seg == 1) ? Wk : Wv;
        transpose_block(W, wqkv + (size_t)seg * EE * CC, CC, EE, bb, t);
    } else if (b < 4096) {
        transpose_block(Wo, wo, EE, CC, b - 3072, t);
    } else if (b < 8192) {
        transpose_block(W1, w1, CC, FF, b - 4096, t);
    } else if (b < 12288) {
        transpose_block(W2, w2, FF, CC, b - 8192, t);
    } else if (b < 13312) {
        convert_block(Wc, wc, b - 12288);
    } else if (b < 17408) {
        convert_block(x, x16, b - 13312);
    } else {
        const int bb = b - 17408;
        const float* src = (bb == 0) ? bq : (bb == 1) ? bk : bv;
        ((float4*)(bqkv + bb * EE))[threadIdx.x] = ((const float4*)src)[threadIdx.x];
    }
}

// ======================= swizzle (128B rows, 8 x 16B chunks) ===============
__device__ __forceinline__ uint32_t sw8(int row, int ch) {
    return (uint32_t)(row * 128 + ((ch ^ (row & 7)) << 4));
}

// ======================= HMMA fp16 GEMM 128x128 (for W1/gF only) ===========
#define STAGE_BYTES 32768
#define ARR_A 0
#define ARR_B 16384
#define GEMM_SMEM (2*STAGE_BYTES)

template<int GELU, int WF32, int WH>
__global__ __launch_bounds__(256, 2) void gemm_mma(
    const __half* __restrict__ A, const __half* __restrict__ Bw,
    const float* __restrict__ bias,
    float* __restrict__ Cf, __half* __restrict__ Ch,
    int M, int N, int K)
{
    extern __shared__ char sm[];
    const uint32_t su = smem_u32(sm);

    const int tid  = threadIdx.x;
    const int wid  = tid >> 5;
    const int lane = tid & 31;
    const int m0 = blockIdx.y * 128;
    const int n0 = blockIdx.x * 128;
    const int wm0 = (wid & 1) * 64;
    const int wn0 = (wid >> 1) * 32;

    float acc[4][4][4];
    #pragma unroll
    for (int mt = 0; mt < 4; mt++)
        #pragma unroll
        for (int nt = 0; nt < 4; nt++)
            #pragma unroll
            for (int i = 0; i < 4; i++) acc[mt][nt][i] = 0.f;

    const int nCh = K >> 6;

    auto issue = [&](int c, int stg) {
        const uint32_t sbase = su + stg * STAGE_BYTES;
        #pragma unroll
        for (int i = 0; i < 4; i++) {
            const int vec = tid + i * 256;
            const int row = vec >> 3;
            const int ch  = vec & 7;
            const uint32_t so = sw8(row, ch);
            const size_t gA = ((size_t)(m0 + row) * K + c * 64 + ch * 8) * 2;
            const size_t gB = ((size_t)(n0 + row) * K + c * 64 + ch * 8) * 2;
            cp16(sbase + ARR_A + so, (const char*)A  + gA);
            cp16(sbase + ARR_B + so, (const char*)Bw + gB);
        }
    };

    issue(0, 0);
    CP_COMMIT();

    const int grp = lane >> 3, wi = lane & 7;

    for (int c = 0; c < nCh; c++) {
        const int stg = c & 1;
        CP_WAIT(0);
        __syncthreads();
        if (c + 1 < nCh) {
            issue(c + 1, stg ^ 1);
            CP_COMMIT();
        }

        const uint32_t sbase = su + stg * STAGE_BYTES;

        #pragma unroll
        for (int ks = 0; ks < 4; ks++) {
            uint32_t bfr[4][2];
            const int brow_base = wn0 + wi + ((grp >> 1) << 3);
            const int bchunk = ks * 2 + (grp & 1);
            #pragma unroll
            for (int bt = 0; bt < 2; bt++) {
                uint32_t r4[4];
                const int br = brow_base + bt * 16;
                ldsm_x4(r4, sbase + ARR_B + sw8(br, bchunk));
                bfr[bt*2][0]   = r4[0]; bfr[bt*2][1]   = r4[1];
                bfr[bt*2+1][0] = r4[2]; bfr[bt*2+1][1] = r4[3];
            }

            const int arow = wm0 + (lane & 15);
            const int achunk = ks * 2 + (lane >> 4);
            uint32_t a[4][4];
            #pragma unroll
            for (int mt = 0; mt < 4; mt++)
                ldsm_x4(a[mt], sbase + ARR_A + sw8(arow + mt * 16, achunk));
            #pragma unroll
            for (int mt = 0; mt < 4; mt++)
                #pragma unroll
                for (int nt = 0; nt < 4; nt++)
                    mma16816(acc[mt][nt], a[mt][0], a[mt][1], a[mt][2], a[mt][3],
                             bfr[nt][0], bfr[nt][1]);
        }
    }

    const int er = lane >> 2;
    const int ec = (lane & 3) * 2;
    #pragma unroll
    for (int mt = 0; mt < 4; mt++) {
        #pragma unroll
        for (int nt = 0; nt < 4; nt++) {
            const int col = n0 + wn0 + nt * 8 + ec;
            const float b0 = bias[col], b1 = bias[col + 1];
            const int rA = m0 + wm0 + mt * 16 + er;
            const int rB = rA + 8;
            float v00 = acc[mt][nt][0] + b0;
            float v01 = acc[mt][nt][1] + b1;
            float v10 = acc[mt][nt][2] + b0;
            float v11 = acc[mt][nt][3] + b1;
            if (GELU) {
                v00 = 0.5f * v00 * (1.0f + erff(v00 * 0.70710678118654752f));
                v01 = 0.5f * v01 * (1.0f + erff(v01 * 0.70710678118654752f));
                v10 = 0.5f * v10 * (1.0f + erff(v10 * 0.70710678118654752f));
                v11 = 0.5f * v11 * (1.0f + erff(v11 * 0.70710678118654752f));
            }
            if (WF32) {
                *(float2*)(Cf + (size_t)rA * N + col) = make_float2(v00, v01);
                *(float2*)(Cf + (size_t)rB * N + col) = make_float2(v10, v11);
            }
            if (WH) {
                *(__half2*)(Ch + (size_t)rA * N + col) =
                    __halves2half2(__float2half_rn(v00), __float2half_rn(v01));
                *(__half2*)(Ch + (size_t)rB * N + col) =
                    __halves2half2(__float2half_rn(v10), __float2half_rn(v11));
            }
        }
    }
}

// ======================= HMMA fp16 GEMM 64x64 (quantization-friendly) ======
// 128 threads (4 warps, warp tile 32x32). Same BK=64, 2-stage, 1 sync.
// Smem/stage: A 8KB + B 8KB = 16KB; 2 stages = 32KB; 4 CTAs/SM.
#define STAGE64 16384
#define A64_OFF 0
#define B64_OFF 8192
#define GEMM64_SMEM (2*STAGE64)

template<int WF32, int WH>
__global__ __launch_bounds__(128, 4) void gemm_mma64(
    const __half* __restrict__ A, const __half* __restrict__ Bw,
    const float* __restrict__ bias,
    float* __restrict__ Cf, __half* __restrict__ Ch,
    int M, int N, int K)
{
    extern __shared__ char sm[];
    const uint32_t su = smem_u32(sm);

    const int tid  = threadIdx.x;
    const int wid  = tid >> 5;        // 0..3
    const int lane = tid & 31;
    const int m0 = blockIdx.y * 64;
    const int n0 = blockIdx.x * 64;
    const int wm0 = (wid & 1) * 32;
    const int wn0 = (wid >> 1) * 32;

    float acc[2][4][4];
    #pragma unroll
    for (int mt = 0; mt < 2; mt++)
        #pragma unroll
        for (int nt = 0; nt < 4; nt++)
            #pragma unroll
            for (int i = 0; i < 4; i++) acc[mt][nt][i] = 0.f;

    const int nCh = K >> 6;

    auto issue = [&](int c, int stg) {
        const uint32_t sbase = su + stg * STAGE64;
        #pragma unroll
        for (int i = 0; i < 4; i++) {
            const int vec = tid + i * 128;   // 0..511
            const int row = vec >> 3;        // 0..63
            const int ch  = vec & 7;
            const uint32_t so = sw8(row, ch);
            const size_t gA = ((size_t)(m0 + row) * K + c * 64 + ch * 8) * 2;
            const size_t gB = ((size_t)(n0 + row) * K + c * 64 + ch * 8) * 2;
            cp16(sbase + A64_OFF + so, (const char*)A  + gA);
            cp16(sbase + B64_OFF + so, (const char*)Bw + gB);
        }
    };

    issue(0, 0);
    CP_COMMIT();

    const int grp = lane >> 3, wi = lane & 7;

    for (int c = 0; c < nCh; c++) {
        const int stg = c & 1;
        CP_WAIT(0);
        __syncthreads();
        if (c + 1 < nCh) {
            issue(c + 1, stg ^ 1);
            CP_COMMIT();
        }

        const uint32_t sbase = su + stg * STAGE64;

        #pragma unroll
        for (int ks = 0; ks < 4; ks++) {
            // B fragments: 32 rows from wn0
            uint32_t bfr[4][2];
            const int brow_base = wn0 + wi + ((grp >> 1) << 3);
            const int bchunk = ks * 2 + (grp & 1);
            #pragma unroll
            for (int bt = 0; bt < 2; bt++) {
                uint32_t r4[4];
                const int br = brow_base + bt * 16;
                ldsm_x4(r4, sbase + B64_OFF + sw8(br, bchunk));
                bfr[bt*2][0]   = r4[0]; bfr[bt*2][1]   = r4[1];
                bfr[bt*2+1][0] = r4[2]; bfr[bt*2+1][1] = r4[3];
            }

            // A fragments: 32 rows from wm0
            const int arow = wm0 + (lane & 15);
            const int achunk = ks * 2 + (lane >> 4);
            uint32_t a[2][4];
            #pragma unroll
            for (int mt = 0; mt < 2; mt++)
                ldsm_x4(a[mt], sbase + A64_OFF + sw8(arow + mt * 16, achunk));

            #pragma unroll
            for (int mt = 0; mt < 2; mt++)
                #pragma unroll
                for (int nt = 0; nt < 4; nt++)
                    mma16816(acc[mt][nt], a[mt][0], a[mt][1], a[mt][2], a[mt][3],
                             bfr[nt][0], bfr[nt][1]);
        }
    }

    const int er = lane >> 2;
    const int ec = (lane & 3) * 2;
    #pragma unroll
    for (int mt = 0; mt < 2; mt++) {
        #pragma unroll
        for (int nt = 0; nt < 4; nt++) {
            const int col = n0 + wn0 + nt * 8 + ec;
            const float b0 = bias[col], b1 = bias[col + 1];
            const int rA = m0 + wm0 + mt * 16 + er;
            const int rB = rA + 8;
            float v00 = acc[mt][nt][0] + b0;
            float v01 = acc[mt][nt][1] + b1;
            float v10 = acc[mt][nt][2] + b0;
            float v11 = acc[mt][nt][3] + b1;
            if (WF32) {
                *(float2*)(Cf + (size_t)rA * N + col) = make_float2(v00, v01);
                *(float2*)(Cf + (size_t)rB * N + col) = make_float2(v10, v11);
            }
            if (WH) {
                *(__half2*)(Ch + (size_t)rA * N + col) =
                    __halves2half2(__float2half_rn(v00), __float2half_rn(v01));
                *(__half2*)(Ch + (size_t)rB * N + col) =
                    __halves2half2(__float2half_rn(v10), __float2half_rn(v11));
            }
        }
    }
}

// ======================= tensor-core flash attention (R16) ==================
#define ASM_Q   0
#define KBUF(b) (16384 + (b) * 16384)
#define VBUF(b) (16384 + (b) * 16384 + 8192)
#define ATTN_SMEM 49152
#define NSCH (TT/64)   // 32
#define SCALE2 0.18033688011112042f   // 0.125 * log2(e)

__global__ void __launch_bounds__(256, 2) attn_mma(
    const __half* __restrict__ QKVp, __half* __restrict__ O)
{
    extern __shared__ char sm[];
    const uint32_t su = smem_u32(sm);

    const int tid  = threadIdx.x;
    const int wid  = tid >> 5;
    const int lane = tid & 31;
    const int q0 = blockIdx.x * 128;
    const int bh = blockIdx.y;
    const int b  = bh >> 4;
    const int h  = bh & 15;
    const size_t mrow0 = (size_t)b * TT;
    const size_t qbase = (mrow0 + q0) * QKV + h * HS;

    const int wm  = wid * 16;
    const int grp = lane >> 3, wi = lane & 7;

    #pragma unroll
    for (int i = 0; i < 4; i++) {
        int vec = tid + i * 256;
        int row = vec >> 3, ch = vec & 7;
        const size_t g = (qbase + (size_t)row * QKV + ch * 8) * 2;
        cp16(su + ASM_Q + sw8(row, ch), (const char*)QKVp + g);
    }
    CP_COMMIT();

    auto issueKV = [&](int s, int stg) {
        const size_t kb = ((mrow0 + (size_t)s * 64) * QKV + EE + h * HS) * 2;
        #pragma unroll
        for (int i = 0; i < 2; i++) {
            int vec = tid + i * 256;
            int row = vec >> 3, ch = vec & 7;
            const size_t off = ((size_t)row * QKV + ch * 8) * 2;
            cp16(su + KBUF(stg) + sw8(row, ch), (const char*)QKVp + kb + off);
            cp16(su + VBUF(stg) + sw8(row, ch), (const char*)QKVp + kb + EE*2 + off);
        }
    };
    issueKV(0, 0);
    CP_COMMIT();

    CP_WAIT(0);
    __syncthreads();

    uint32_t qa[4][4];
    {
        const int arow = wm + (lane & 15);
        #pragma unroll
        for (int ks = 0; ks < 4; ks++) {
            const int achunk = ks * 2 + (lane >> 4);
            ldsm_x4(qa[ks], su + ASM_Q + sw8(arow, achunk));
        }
    }

    float m0 = -1e30f, m1 = -1e30f, l0 = 0.f, l1 = 0.f;
    float oacc[8][4];
    #pragma unroll
    for (int nt = 0; nt < 8; nt++)
        #pragma unroll
        for (int i = 0; i < 4; i++) oacc[nt][i] = 0.f;

    for (int s = 0; s < NSCH; s++) {
        const int stg = s & 1;
        if (s > 0) {
            CP_WAIT(0);
            __syncthreads();
        }
        if (s + 1 < NSCH) {
            issueKV(s + 1, stg ^ 1);
            CP_COMMIT();
        }

        const uint32_t kbase = su + KBUF(stg);
        const uint32_t vbase = su + VBUF(stg);

        float sacc[8][4];
        #pragma unroll
        for (int nt = 0; nt < 8; nt++)
            #pragma unroll
            for (int i = 0; i < 4; i++) sacc[nt][i] = 0.f;

        #pragma unroll
        for (int ks = 0; ks < 4; ks++) {
            uint32_t kf[8][2];
            #pragma unroll
            for (int bt = 0; bt < 4; bt++) {
                const int br = wi + ((grp >> 1) << 3) + bt * 16;
                const int bch = ks * 2 + (grp & 1);
                uint32_t r4[4];
                ldsm_x4(r4, kbase + sw8(br, bch));
                kf[bt*2][0] = r4[0]; kf[bt*2][1] = r4[1];
                kf[bt*2+1][0] = r4[2]; kf[bt*2+1][1] = r4[3];
            }
            #pragma unroll
            for (int nt = 0; nt < 8; nt++)
                mma16816(sacc[nt], qa[ks][0], qa[ks][1], qa[ks][2], qa[ks][3],
                         kf[nt][0], kf[nt][1]);
        }

        float rmax0 = -1e30f, rmax1 = -1e30f;
        #pragma unroll
        for (int nt = 0; nt < 8; nt++) {
            #pragma unroll
            for (int i = 0; i < 4; i++) sacc[nt][i] *= SCALE2;
            rmax0 = fmaxf(rmax0, fmaxf(sacc[nt][0], sacc[nt][1]));
            rmax1 = fmaxf(rmax1, fmaxf(sacc[nt][2], sacc[nt][3]));
        }
        #pragma unroll
        for (int msk = 1; msk < 4; msk <<= 1) {
            rmax0 = fmaxf(rmax0, __shfl_xor_sync(0xffffffffu, rmax0, msk));
            rmax1 = fmaxf(rmax1, __shfl_xor_sync(0xffffffffu, rmax1, msk));
        }
        const float nm0 = fmaxf(m0, rmax0);
        const float nm1 = fmaxf(m1, rmax1);
        const float corr0 = ex2(m0 - nm0);
        const float corr1 = ex2(m1 - nm1);

        uint32_t pa[4][4];
        float sum0 = 0.f, sum1 = 0.f;
        #pragma unroll
        for (int nt = 0; nt < 8; nt++) {
            float p0 = ex2(sacc[nt][0] - nm0);
            float p1 = ex2(sacc[nt][1] - nm0);
            float p2 = ex2(sacc[nt][2] - nm1);
            float p3 = ex2(sacc[nt][3] - nm1);
            sum0 += p0 + p1;
            sum1 += p2 + p3;
            const int kt = nt >> 1, hf = nt & 1;
            pa[kt][hf*2]   = packh(__float2half_rn(p0), __float2half_rn(p1));
            pa[kt][hf*2+1] = packh(__float2half_rn(p2), __float2half_rn(p3));
        }
        #pragma unroll
        for (int msk = 1; msk < 4; msk <<= 1) {
            sum0 += __shfl_xor_sync(0xffffffffu, sum0, msk);
            sum1 += __shfl_xor_sync(0xffffffffu, sum1, msk);
        }
        l0 = l0 * corr0 + sum0;
        l1 = l1 * corr1 + sum1;
        m0 = nm0; m1 = nm1;
        #pragma unroll
        for (int nt = 0; nt < 8; nt++) {
            oacc[nt][0] *= corr0; oacc[nt][1] *= corr0;
            oacc[nt][2] *= corr1; oacc[nt][3] *= corr1;
        }

        #pragma unroll
        for (int ks = 0; ks < 4; ks++) {
            uint32_t vf[8][2];
            #pragma unroll
            for (int bt = 0; bt < 4; bt++) {
                const int key_row = ks * 16 + (grp & 1) * 8 + wi;
                const int dim_ch  = bt * 2 + (grp >> 1);
                uint32_t r4[4];
                ldsm_x4_t(r4, vbase + sw8(key_row, dim_ch));
                vf[bt*2][0] = r4[0]; vf[bt*2][1] = r4[1];
                vf[bt*2+1][0] = r4[2]; vf[bt*2+1][1] = r4[3];
            }
            #pragma unroll
            for (int nt = 0; nt < 8; nt++)
                mma16816(oacc[nt], pa[ks][0], pa[ks][1], pa[ks][2], pa[ks][3],
                         vf[nt][0], vf[nt][1]);
        }
    }

    const float inv0 = 1.0f / l0;
    const float inv1 = 1.0f / l1;
    const int r = lane >> 2;
    const int qcol = 2 * (lane & 3);
    const size_t row0 = (mrow0 + q0 + wm + r) * EE + h * HS;
    const size_t row1 = row0 + (size_t)8 * EE;
    #pragma unroll
    for (int nt = 0; nt < 8; nt++) {
        const int col = nt * 8 + qcol;
        *(__half2*)(O + row0 + col) = __halves2half2(
            __float2half_rn(oacc[nt][0] * inv0), __float2half_rn(oacc[nt][1] * inv0));
        *(__half2*)(O + row1 + col) = __halves2half2(
            __float2half_rn(oacc[nt][2] * inv1), __float2half_rn(oacc[nt][3] * inv1));
    }
}

// ======================= residual add + LayerNorm ==========================
template<int RF32>
__global__ __launch_bounds__(256) void add_ln(
    const float* __restrict__ af, const __half* __restrict__ ah,
    const __half* __restrict__ bsrc,
    const float* __restrict__ g, const float* __restrict__ beta,
    __half* __restrict__ oh)
{
    const int row = blockIdx.x;
    const int tid = threadIdx.x;
    float4 av;
    if (RF32) {
        av = ((const float4*)(af + (size_t)row * CC))[tid];
    } else {
        const __half2 a01 = ((const __half2*)(ah + (size_t)row * CC))[tid*2];
        const __half2 a23 = ((const __half2*)(ah + (size_t)row * CC))[tid*2 + 1];
        const float2 f01 = __half22float2(a01);
        const float2 f23 = __half22float2(a23);
        av = make_float4(f01.x, f01.y, f23.x, f23.y);
    }
    const __half2 h01 = ((const __half2*)(bsrc + (size_t)row * CC))[tid*2];
    const __half2 h23 = ((const __half2*)(bsrc + (size_t)row * CC))[tid*2 + 1];
    const float2 b01 = __half22float2(h01);
    const float2 b23 = __half22float2(h23);
    float4 v = make_float4(av.x + b01.x, av.y + b01.y, av.z + b23.x, av.w + b23.y);

    float s  = v.x + v.y + v.z + v.w;
    float ss = v.x*v.x + v.y*v.y + v.z*v.z + v.w*v.w;
    #pragma unroll
    for (int msk = 16; msk; msk >>= 1) {
        s  += __shfl_xor_sync(0xffffffffu, s,  msk);
        ss += __shfl_xor_sync(0xffffffffu, ss, msk);
    }
    __shared__ float ws[8], wss[8];
    __shared__ float mu_s, rstd_s;
    const int w = tid >> 5, lane = tid & 31;
    if (lane == 0) { ws[w] = s; wss[w] = ss; }
    __syncthreads();
    if (tid == 0) {
        float S = 0.f, SS = 0.f;
        #pragma unroll
        for (int i = 0; i < 8; i++) { S += ws[i]; SS += wss[i]; }
        float mu  = S * (1.0f / CC);
        float var = SS * (1.0f / CC) - mu * mu;
        mu_s   = mu;
        rstd_s = rsqrtf(var + 1e-5f);
    }
    __syncthreads();
    const float mu = mu_s, rstd = rstd_s;
    const float4 gv = ((const float4*)g)[tid];
    const float4 bv2 = ((const float4*)beta)[tid];
    float4 ov;
    ov.x = (v.x - mu) * rstd * gv.x + bv2.x;
    ov.y = (v.y - mu) * rstd * gv.y + bv2.y;
    ov.z = (v.z - mu) * rstd * gv.z + bv2.z;
    ov.w = (v.w - mu) * rstd * gv.w + bv2.w;

    size_t o = (size_t)row * CC + tid * 4;
    *(__half2*)(oh + o)     = __halves2half2(__float2half_rn(ov.x), __float2half_rn(ov.y));
    *(__half2*)(oh + o + 2) = __halves2half2(__float2half_rn(ov.z), __float2half_rn(ov.w));
}

// ======================= launch ============================================
extern "C" void kernel_launch(void* const* d_in, const int* in_sizes, int n_in,
                              void* d_out, int out_size)
{
    const float* x     = (const float*)d_in[0];
    const float* Wq    = (const float*)d_in[1];
    const float* bq    = (const float*)d_in[2];
    const float* Wk    = (const float*)d_in[3];
    const float* bk    = (const float*)d_in[4];
    const float* Wv    = (const float*)d_in[5];
    const float* bv    = (const float*)d_in[6];
    const float* Wo    = (const float*)d_in[7];
    const float* bo    = (const float*)d_in[8];
    const float* ln1_g = (const float*)d_in[9];
    const float* ln1_b = (const float*)d_in[10];
    const float* W1    = (const float*)d_in[11];
    const float* b1    = (const float*)d_in[12];
    const float* W2    = (const float*)d_in[13];
    const float* b2    = (const float*)d_in[14];
    const float* ln2_g = (const float*)d_in[15];
    const float* ln2_b = (const float*)d_in[16];
    const float* Wc    = (const float*)d_in[17];
    const float* bc    = (const float*)d_in[18];
    float* out = (float*)d_out;

    float *bqkv;
    cudaGetSymbolAddress((void**)&bqkv, g_bqkv);

    __half *tmph,*x16,*qkv,*a16,*o116,*f16,*o216,*wqkv,*wo,*w1,*w2,*wc;
    cudaGetSymbolAddress((void**)&tmph, g_tmph);
    cudaGetSymbolAddress((void**)&x16,  g_x16);
    cudaGetSymbolAddress((void**)&qkv,  g_qkv);
    cudaGetSymbolAddress((void**)&a16,  g_a16);
    cudaGetSymbolAddress((void**)&o116, g_o116);
    cudaGetSymbolAddress((void**)&f16,  g_f16);
    cudaGetSymbolAddress((void**)&o216, g_o216);
    cudaGetSymbolAddress((void**)&wqkv, g_wqkv);
    cudaGetSymbolAddress((void**)&wo,   g_wo);
    cudaGetSymbolAddress((void**)&w1,   g_w1);
    cudaGetSymbolAddress((void**)&w2,   g_w2);
    cudaGetSymbolAddress((void**)&wc,   g_wc);

    cudaFuncSetAttribute(gemm_mma<1,0,1>,
                         cudaFuncAttributeMaxDynamicSharedMemorySize, GEMM_SMEM);
    cudaFuncSetAttribute(gemm_mma64<0,1>,
                         cudaFuncAttributeMaxDynamicSharedMemorySize, GEMM64_SMEM);
    cudaFuncSetAttribute(gemm_mma64<1,0>,
                         cudaFuncAttributeMaxDynamicSharedMemorySize, GEMM64_SMEM);
    cudaFuncSetAttribute(attn_mma,
                         cudaFuncAttributeMaxDynamicSharedMemorySize, ATTN_SMEM);

    // --- all prep in ONE launch ---
    prep_all<<<PREP_GRID, 256>>>(Wq, Wk, Wv, Wo, W1, W2, Wc, x, bq, bk, bv,
                                 wqkv, wo, w1, w2, wc, x16, bqkv);

    // --- fused QKV projection (64x64 tiles: 48x64 = 3072 CTAs) ---
    const dim3 gQKV64(QKV/64, MM/64);
    const dim3 gC64(CC/64, MM/64);
    const dim3 gF(FF/128, MM/128);
    gemm_mma64<0,1><<<gQKV64, 128, GEMM64_SMEM>>>(x16, wqkv, bqkv, nullptr, qkv, MM, QKV, CC);

    // --- attention ---
    attn_mma<<<dim3(TT/128, BB*HH), 256, ATTN_SMEM>>>(qkv, a16);

    // --- output projection (fp16 out) + residual + LN1 ---
    gemm_mma64<0,1><<<gC64, 128, GEMM64_SMEM>>>(a16, wo, bo, nullptr, tmph, MM, CC, EE);
    add_ln<1><<<MM, 256>>>(x, nullptr, tmph, ln1_g, ln1_b, o116);

    // --- FFN ---
    gemm_mma<1,0,1><<<gF, 256, GEMM_SMEM>>>(o116, w1, b1, nullptr, f16, MM, FF, CC);
    gemm_mma64<0,1><<<gC64, 128, GEMM64_SMEM>>>(f16, w2, b2, nullptr, tmph, MM, CC, FF);
    add_ln<0><<<MM, 256>>>(nullptr, o116, tmph, ln2_g, ln2_b, o216);

    // --- final pointwise conv: out = out2 @ Wc^T + bc ---
    gemm_mma64<1,0><<<gC64, 128, GEMM64_SMEM>>>(o216, wc, bc, out, nullptr, MM, CC, CC);
}